// round 1
// baseline (speedup 1.0000x reference)
#include <cuda_runtime.h>

#define NU 50000
#define NI 30000
#define NN 80000
#define NE 1600000
#define SCAN_BLOCKS 79   // ceil(80000/1024)

// ---------------- scratch (device globals; no allocation allowed) ----------
__device__ int    g_deg[NN];
__device__ int    g_off[NN + 1];
__device__ int    g_cur[NN];
__device__ int    g_bsum[128];
__device__ int    g_col[NE];
__device__ float4 g_xv[NN * 16];
__device__ float4 g_xt[NN * 16];
__device__ float4 g_av[NN * 16];
__device__ float4 g_at[NN * 16];

__device__ __forceinline__ float leaky(float x) {
    return x > 0.f ? x : 0.01f * x;
}

// ---------------- CSR build -------------------------------------------------
__global__ void k_zero() {
    int i = blockIdx.x * blockDim.x + threadIdx.x;
    if (i < NN) g_deg[i] = 0;
}

__global__ void k_hist(const int* __restrict__ row) {
    int e = blockIdx.x * blockDim.x + threadIdx.x;
    if (e < NE) atomicAdd(&g_deg[row[e]], 1);
}

__global__ void k_scan1() {  // per-block inclusive scan of g_deg
    __shared__ int s[1024];
    int tid = threadIdx.x;
    int i = blockIdx.x * 1024 + tid;
    int v = (i < NN) ? g_deg[i] : 0;
    s[tid] = v;
    __syncthreads();
#pragma unroll
    for (int off = 1; off < 1024; off <<= 1) {
        int t = (tid >= off) ? s[tid - off] : 0;
        __syncthreads();
        s[tid] += t;
        __syncthreads();
    }
    if (i < NN) g_off[i + 1] = s[tid];
    if (tid == 1023) g_bsum[blockIdx.x] = s[1023];
}

__global__ void k_scan2() {  // exclusive scan of block sums (tiny, serial)
    if (threadIdx.x == 0) {
        int run = 0;
        for (int b = 0; b < SCAN_BLOCKS; b++) {
            int t = g_bsum[b];
            g_bsum[b] = run;
            run += t;
        }
    }
}

__global__ void k_scan3() {
    int i = blockIdx.x * blockDim.x + threadIdx.x;
    if (i < NN) g_off[i + 1] += g_bsum[i >> 10];
    if (i == 0) g_off[0] = 0;
}

__global__ void k_cur() {
    int i = blockIdx.x * blockDim.x + threadIdx.x;
    if (i < NN) g_cur[i] = g_off[i];
}

__global__ void k_fill(const int* __restrict__ row, const int* __restrict__ col) {
    int e = blockIdx.x * blockDim.x + threadIdx.x;
    if (e < NE) {
        int r = row[e];
        int p = atomicAdd(&g_cur[r], 1);
        g_col[p] = col[e];
    }
}

// ---------------- init: x = L2-normalize(cat(pref, feat)) ------------------
__global__ void k_init(const float* __restrict__ pref,
                       const float* __restrict__ feat, int tower) {
    int w = (blockIdx.x * blockDim.x + threadIdx.x) >> 5;
    if (w >= NN) return;
    int lane = threadIdx.x & 31;
    const float2* src = (w < NU) ? (const float2*)(pref) + w * 32
                                 : (const float2*)(feat) + (w - NU) * 32;
    float2 v = src[lane];
    float ss = v.x * v.x + v.y * v.y;
#pragma unroll
    for (int o = 16; o > 0; o >>= 1) ss += __shfl_xor_sync(0xffffffffu, ss, o);
    float inv = 1.0f / fmaxf(sqrtf(ss), 1e-12f);
    float2 o = make_float2(v.x * inv, v.y * inv);
    float2* dst = tower ? (float2*)g_xt : (float2*)g_xv;
    dst[w * 32 + lane] = o;
}

// ---------------- aggregation: scatter-mean for BOTH towers ----------------
__global__ void k_agg() {
    int w = (blockIdx.x * blockDim.x + threadIdx.x) >> 5;
    if (w >= NN) return;
    int lane = threadIdx.x & 31;
    int l = lane & 15;
    const float4* __restrict__ src = (lane < 16) ? g_xv : g_xt;
    float4* dst = (lane < 16) ? g_av : g_at;
    int beg = g_off[w], end = g_off[w + 1];
    float4 acc = make_float4(0.f, 0.f, 0.f, 0.f);
    for (int e = beg; e < end; e++) {
        int c = g_col[e];
        float4 v = src[c * 16 + l];
        acc.x += v.x; acc.y += v.y; acc.z += v.z; acc.w += v.w;
    }
    float inv = 1.0f / (float)(end - beg);
    dst[w * 16 + l] = make_float4(acc.x * inv, acc.y * inv, acc.z * inv, acc.w * inv);
}

// ---------------- fused dense layer -----------------------------------------
// x_next = leaky( leaky(agg@W0^T + b0)@W2^T + b2 + leaky(x@W1^T + b1) + id )
// W stored transposed in smem as float2 pairs: Ws[m][k*32 + lane] = (W[2l][k], W[2l+1][k])
__device__ __forceinline__ float2 mv(const float2* __restrict__ Wm, float2 v, int lane) {
    float2 acc = make_float2(0.f, 0.f);
#pragma unroll
    for (int k = 0; k < 64; k++) {
        float sv = __shfl_sync(0xffffffffu, (k & 1) ? v.y : v.x, k >> 1);
        float2 w = Wm[(k << 5) + lane];
        acc.x = fmaf(sv, w.x, acc.x);
        acc.y = fmaf(sv, w.y, acc.y);
    }
    return acc;
}

__global__ void k_dense(int tower, const float* __restrict__ id_emb,
                        const float* __restrict__ W, const float* __restrict__ B) {
    __shared__ float2 Ws[3 * 2048];  // 48 KB
    int t = threadIdx.x;
#pragma unroll
    for (int m = 0; m < 3; m++) {
        const float* Wm = W + m * 4096;
        for (int idx = t; idx < 2048; idx += blockDim.x) {
            int l = idx & 31, k = idx >> 5;
            Ws[m * 2048 + k * 32 + l] =
                make_float2(Wm[(2 * l) * 64 + k], Wm[(2 * l + 1) * 64 + k]);
        }
    }
    __syncthreads();

    int warp = t >> 5, lane = t & 31;
    float2* xbuf = tower ? (float2*)g_xt : (float2*)g_xv;
    const float2* abuf = tower ? (const float2*)g_at : (const float2*)g_av;
    const float2* id2 = (const float2*)id_emb;

    float2 b0 = make_float2(B[2 * lane],       B[2 * lane + 1]);
    float2 b1 = make_float2(B[64 + 2 * lane],  B[64 + 2 * lane + 1]);
    float2 b2 = make_float2(B[128 + 2 * lane], B[128 + 2 * lane + 1]);

    const float2* W0 = Ws;
    const float2* W1 = Ws + 2048;
    const float2* W2 = Ws + 4096;

    int gw = blockIdx.x * (blockDim.x >> 5) + warp;
    int stride = gridDim.x * (blockDim.x >> 5);
    for (int r = gw; r < NN; r += stride) {
        float2 xr = xbuf[r * 32 + lane];
        float2 ar = abuf[r * 32 + lane];
        float2 idv = id2[r * 32 + lane];

        float2 acc = mv(W1, xr, lane);                       // x @ W1^T
        float2 xhat = make_float2(leaky(acc.x + b1.x) + idv.x,
                                  leaky(acc.y + b1.y) + idv.y);

        acc = mv(W0, ar, lane);                              // agg @ W0^T
        float2 h = make_float2(leaky(acc.x + b0.x), leaky(acc.y + b0.y));

        acc = mv(W2, h, lane);                               // h @ W2^T
        float2 o = make_float2(leaky(acc.x + b2.x + xhat.x),
                               leaky(acc.y + b2.y + xhat.y));
        xbuf[r * 32 + lane] = o;                             // in-place (row-local)
    }
}

// ---------------- final combine ---------------------------------------------
__global__ void k_combine(float4* __restrict__ out) {
    int i = blockIdx.x * blockDim.x + threadIdx.x;
    if (i < NN * 16) {
        float4 a = g_xv[i], b = g_xt[i];
        out[i] = make_float4(0.5f * (a.x + b.x), 0.5f * (a.y + b.y),
                             0.5f * (a.z + b.z), 0.5f * (a.w + b.w));
    }
}

// ---------------- launch ------------------------------------------------------
extern "C" void kernel_launch(void* const* d_in, const int* in_sizes, int n_in,
                              void* d_out, int out_size) {
    const float* v_feat = (const float*)d_in[0];
    const float* t_feat = (const float*)d_in[1];
    const float* id_emb = (const float*)d_in[2];
    const float* v_pref = (const float*)d_in[3];
    const float* t_pref = (const float*)d_in[4];
    const float* v_W    = (const float*)d_in[5];
    const float* v_b    = (const float*)d_in[6];
    const float* t_W    = (const float*)d_in[7];
    const float* t_b    = (const float*)d_in[8];
    const int*   edges  = (const int*)d_in[9];
    const int* row = edges;
    const int* col = edges + NE;
    float4* out = (float4*)d_out;

    // CSR build (once per call, reused by both layers & towers)
    k_zero<<<(NN + 255) / 256, 256>>>();
    k_hist<<<(NE + 255) / 256, 256>>>(row);
    k_scan1<<<SCAN_BLOCKS, 1024>>>();
    k_scan2<<<1, 32>>>();
    k_scan3<<<(NN + 255) / 256, 256>>>();
    k_cur<<<(NN + 255) / 256, 256>>>();
    k_fill<<<(NE + 255) / 256, 256>>>(row, col);

    // normalized initial features
    k_init<<<10000, 256>>>(v_pref, v_feat, 0);
    k_init<<<10000, 256>>>(t_pref, t_feat, 1);

    // 2 GCN layers
    for (int layer = 0; layer < 2; layer++) {
        k_agg<<<10000, 256>>>();
        k_dense<<<592, 256>>>(0, id_emb, v_W + layer * 3 * 4096, v_b + layer * 3 * 64);
        k_dense<<<592, 256>>>(1, id_emb, t_W + layer * 3 * 4096, t_b + layer * 3 * 64);
    }

    k_combine<<<(NN * 16 + 255) / 256, 256>>>(out);
}

// round 2
// speedup vs baseline: 1.0730x; 1.0730x over previous
#include <cuda_runtime.h>

#define NU 50000
#define NN 80000
#define NE 1600000
#define NB_SCAN 79   // ceil(80000/1024)

// ---------------- scratch (device globals; no allocation allowed) ----------
__device__ int    g_deg[NN];
__device__ int    g_off[NN + 1];
__device__ int    g_cur[NN + 1];
__device__ int    g_bsum[NB_SCAN];
__device__ int    g_col[NE];
__device__ float4 g_bufA[2 * NN * 16];   // [tower][node][16 float4] = 41 MB
__device__ float4 g_bufB[2 * NN * 16];

__device__ __forceinline__ float leaky(float x) {
    return fmaxf(x, 0.01f * x);   // branch-free leaky relu
}

// ---------------- init: zero deg + x = L2-normalize(cat(pref, feat)) -------
__global__ void k_init(const float* __restrict__ v_pref, const float* __restrict__ v_feat,
                       const float* __restrict__ t_pref, const float* __restrict__ t_feat) {
    int gid = blockIdx.x * blockDim.x + threadIdx.x;
    if (gid < NN) g_deg[gid] = 0;
    int w = gid >> 5;
    if (w >= 2 * NN) return;
    int lane = gid & 31;
    int tower = (w >= NN) ? 1 : 0;
    int n = w - tower * NN;
    const float2* src;
    if (tower == 0)
        src = (n < NU) ? (const float2*)v_pref + n * 32 : (const float2*)v_feat + (n - NU) * 32;
    else
        src = (n < NU) ? (const float2*)t_pref + n * 32 : (const float2*)t_feat + (n - NU) * 32;
    float2 v = src[lane];
    float ss = v.x * v.x + v.y * v.y;
#pragma unroll
    for (int o = 16; o > 0; o >>= 1) ss += __shfl_xor_sync(0xffffffffu, ss, o);
    float inv = 1.0f / fmaxf(sqrtf(ss), 1e-12f);
    ((float2*)g_bufA)[w * 32 + lane] = make_float2(v.x * inv, v.y * inv);
}

// ---------------- CSR build -------------------------------------------------
__global__ void k_hist(const int* __restrict__ row) {
    int e = blockIdx.x * blockDim.x + threadIdx.x;
    if (e < NE) atomicAdd(&g_deg[row[e]], 1);
}

__global__ void k_scan1() {  // per-block inclusive scan of g_deg
    __shared__ int s[1024];
    int tid = threadIdx.x;
    int i = blockIdx.x * 1024 + tid;
    int v = (i < NN) ? g_deg[i] : 0;
    s[tid] = v;
    __syncthreads();
#pragma unroll
    for (int off = 1; off < 1024; off <<= 1) {
        int t = (tid >= off) ? s[tid - off] : 0;
        __syncthreads();
        s[tid] += t;
        __syncthreads();
    }
    if (i < NN) g_off[i + 1] = s[tid];
    if (tid == 1023) g_bsum[blockIdx.x] = s[1023];
}

// merged scan2+scan3+cur: each block computes its own bsum prefix internally
__global__ void k_scan2f() {
    __shared__ int s_pref;
    int tid = threadIdx.x;
    if (tid < 32) {
        int sum = 0;
        for (int j = tid; j < blockIdx.x; j += 32) sum += g_bsum[j];
#pragma unroll
        for (int o = 16; o > 0; o >>= 1) sum += __shfl_xor_sync(0xffffffffu, sum, o);
        if (tid == 0) s_pref = sum;
    }
    __syncthreads();
    int prefix = s_pref;
    int i = blockIdx.x * 1024 + tid;
    if (i < NN) {
        int v = g_off[i + 1] + prefix;
        g_off[i + 1] = v;
        g_cur[i + 1] = v;
    }
    if (i == 0) { g_off[0] = 0; g_cur[0] = 0; }
}

__global__ void k_fill(const int* __restrict__ row, const int* __restrict__ col) {
    int e = blockIdx.x * blockDim.x + threadIdx.x;
    if (e < NE) {
        int r = row[e];
        int p = atomicAdd(&g_cur[r], 1);
        g_col[p] = col[e];
    }
}

// ---------------- fused layer: scatter-mean + 3 matvecs, per tower ----------
// W stored transposed in smem: Ws[m][(k<<5)+l] = (W[2l][k], W[2l+1][k])
__device__ __forceinline__ float2 mv(const float2* __restrict__ Wm, float2 v, int lane) {
    float2 acc = make_float2(0.f, 0.f);
#pragma unroll
    for (int k = 0; k < 64; k++) {
        float sv = __shfl_sync(0xffffffffu, (k & 1) ? v.y : v.x, k >> 1);
        float2 w = Wm[(k << 5) + lane];
        acc.x = fmaf(sv, w.x, acc.x);
        acc.y = fmaf(sv, w.y, acc.y);
    }
    return acc;
}

__global__ void __launch_bounds__(256)
k_layer(const float4* __restrict__ xin4, float4* __restrict__ xout4,
        const float* __restrict__ Wv, const float* __restrict__ Bv,
        const float* __restrict__ Wt, const float* __restrict__ Bt,
        const float* __restrict__ id_emb) {
    __shared__ float2 Ws[3 * 2048];  // 48 KB
    int tower = blockIdx.y;
    const float* W = tower ? Wt : Wv;
    const float* B = tower ? Bt : Bv;
    int t = threadIdx.x;
#pragma unroll
    for (int m = 0; m < 3; m++) {
        const float* Wm = W + m * 4096;
        for (int idx = t; idx < 2048; idx += 256) {
            int l = idx & 31, k = idx >> 5;
            Ws[m * 2048 + k * 32 + l] =
                make_float2(Wm[(2 * l) * 64 + k], Wm[(2 * l + 1) * 64 + k]);
        }
    }
    __syncthreads();

    int lane = t & 31, warp = t >> 5;
    const float2* xin = (const float2*)xin4 + (size_t)tower * (NN * 32);
    float2* xout = (float2*)xout4 + (size_t)tower * (NN * 32);
    const float2* id2 = (const float2*)id_emb;

    float2 b0 = ((const float2*)B)[lane];
    float2 b1 = ((const float2*)(B + 64))[lane];
    float2 b2 = ((const float2*)(B + 128))[lane];
    const float2* W0 = Ws;
    const float2* W1 = Ws + 2048;
    const float2* W2 = Ws + 4096;

    int stride = gridDim.x * 8;
    for (int r = blockIdx.x * 8 + warp; r < NN; r += stride) {
        int beg = g_off[r], end = g_off[r + 1];
        // --------- scatter-mean aggregation (unroll 4 for MLP) ---------
        float2 s0 = make_float2(0.f, 0.f), s1 = make_float2(0.f, 0.f);
        int e = beg;
        for (; e + 4 <= end; e += 4) {
            int c0 = g_col[e], c1 = g_col[e + 1], c2 = g_col[e + 2], c3 = g_col[e + 3];
            float2 v0 = xin[c0 * 32 + lane];
            float2 v1 = xin[c1 * 32 + lane];
            float2 v2 = xin[c2 * 32 + lane];
            float2 v3 = xin[c3 * 32 + lane];
            s0.x += v0.x + v1.x; s0.y += v0.y + v1.y;
            s1.x += v2.x + v3.x; s1.y += v2.y + v3.y;
        }
        for (; e < end; e++) {
            int c = g_col[e];
            float2 v = xin[c * 32 + lane];
            s0.x += v.x; s0.y += v.y;
        }
        float invd = __fdividef(1.0f, (float)(end - beg));
        float2 a = make_float2((s0.x + s1.x) * invd, (s0.y + s1.y) * invd);

        // --------- dense: leaky(leaky(a@W0ᵀ+b0)@W2ᵀ+b2 + leaky(x@W1ᵀ+b1)+id) ---
        float2 xr = xin[r * 32 + lane];
        float2 idv = id2[r * 32 + lane];

        float2 t1 = mv(W1, xr, lane);
        float2 xhat = make_float2(leaky(t1.x + b1.x) + idv.x,
                                  leaky(t1.y + b1.y) + idv.y);
        float2 h = mv(W0, a, lane);
        h = make_float2(leaky(h.x + b0.x), leaky(h.y + b0.y));
        float2 o = mv(W2, h, lane);
        o = make_float2(leaky(o.x + b2.x + xhat.x),
                        leaky(o.y + b2.y + xhat.y));
        xout[r * 32 + lane] = o;
    }
}

// ---------------- final combine ---------------------------------------------
__global__ void k_combine(float4* __restrict__ out) {
    int i = blockIdx.x * blockDim.x + threadIdx.x;
    if (i < NN * 16) {
        float4 a = g_bufA[i], b = g_bufA[NN * 16 + i];
        out[i] = make_float4(0.5f * (a.x + b.x), 0.5f * (a.y + b.y),
                             0.5f * (a.z + b.z), 0.5f * (a.w + b.w));
    }
}

// ---------------- launch ------------------------------------------------------
extern "C" void kernel_launch(void* const* d_in, const int* in_sizes, int n_in,
                              void* d_out, int out_size) {
    const float* v_feat = (const float*)d_in[0];
    const float* t_feat = (const float*)d_in[1];
    const float* id_emb = (const float*)d_in[2];
    const float* v_pref = (const float*)d_in[3];
    const float* t_pref = (const float*)d_in[4];
    const float* v_W    = (const float*)d_in[5];
    const float* v_b    = (const float*)d_in[6];
    const float* t_W    = (const float*)d_in[7];
    const float* t_b    = (const float*)d_in[8];
    const int*   edges  = (const int*)d_in[9];
    const int* row = edges;
    const int* col = edges + NE;
    float4* out = (float4*)d_out;

    float4 *bufA, *bufB;
    cudaGetSymbolAddress((void**)&bufA, g_bufA);
    cudaGetSymbolAddress((void**)&bufB, g_bufB);

    // 1: init (normalize both towers) + zero deg
    k_init<<<20000, 256>>>(v_pref, v_feat, t_pref, t_feat);
    // 2-5: CSR build
    k_hist<<<(NE + 255) / 256, 256>>>(row);
    k_scan1<<<NB_SCAN, 1024>>>();
    k_scan2f<<<NB_SCAN, 1024>>>();
    k_fill<<<(NE + 255) / 256, 256>>>(row, col);

    // 6-7: two fused GCN layers (both towers per launch), ping-pong A->B->A
    dim3 lgrid(296, 2);
    k_layer<<<lgrid, 256>>>(bufA, bufB, v_W, v_b, t_W, t_b, id_emb);
    k_layer<<<lgrid, 256>>>(bufB, bufA, v_W + 3 * 4096, v_b + 3 * 64,
                            t_W + 3 * 4096, t_b + 3 * 64, id_emb);

    // 8: combine
    k_combine<<<(NN * 16 + 255) / 256, 256>>>(out);
}

// round 3
// speedup vs baseline: 1.2891x; 1.2015x over previous
#include <cuda_runtime.h>

#define NU 50000
#define NN 80000
#define NE 1600000
#define NB_SCAN 79   // ceil(80000/1024)

// ---------------- scratch (device globals; no allocation allowed) ----------
__device__ int    g_deg[NN];
__device__ int    g_off[NN + 1];
__device__ int    g_cur[NN + 1];
__device__ unsigned long long g_state[NB_SCAN];   // parallel-lookback scan state
__device__ int    g_col[NE];
__device__ float4 g_bufA[2 * NN * 16];   // [tower][node][16 float4]
__device__ float4 g_bufB[2 * NN * 16];

__device__ __forceinline__ float leaky(float x) {
    return fmaxf(x, 0.01f * x);
}

// ------------- launch 1: normalize both towers + edge histogram -------------
__global__ void k_init_hist(const float* __restrict__ v_pref, const float* __restrict__ v_feat,
                            const float* __restrict__ t_pref, const float* __restrict__ t_feat,
                            const int* __restrict__ row) {
    int gid = blockIdx.x * blockDim.x + threadIdx.x;
    if (gid < NE) atomicAdd(&g_deg[row[gid]], 1);
    int w = gid >> 5;
    if (w >= 2 * NN) return;
    int lane = gid & 31;
    int tower = (w >= NN) ? 1 : 0;
    int n = w - tower * NN;
    const float2* src;
    if (tower == 0)
        src = (n < NU) ? (const float2*)v_pref + n * 32 : (const float2*)v_feat + (n - NU) * 32;
    else
        src = (n < NU) ? (const float2*)t_pref + n * 32 : (const float2*)t_feat + (n - NU) * 32;
    float2 v = src[lane];
    float ss = v.x * v.x + v.y * v.y;
#pragma unroll
    for (int o = 16; o > 0; o >>= 1) ss += __shfl_xor_sync(0xffffffffu, ss, o);
    float inv = 1.0f / fmaxf(sqrtf(ss), 1e-12f);
    ((float2*)g_bufA)[w * 32 + lane] = make_float2(v.x * inv, v.y * inv);
}

// ------------- launch 2: single-kernel scan (parallel lookback) -------------
__global__ void k_scan() {
    __shared__ int s[1024];
    __shared__ int s_prev;
    int tid = threadIdx.x;
    int i = blockIdx.x * 1024 + tid;
    int v = (i < NN) ? g_deg[i] : 0;
    s[tid] = v;
    __syncthreads();
#pragma unroll
    for (int off = 1; off < 1024; off <<= 1) {
        int t = (tid >= off) ? s[tid - off] : 0;
        __syncthreads();
        s[tid] += t;
        __syncthreads();
    }
    // publish own aggregate (flag in high 32 bits)
    if (tid == 0) {
        unsigned long long mine = (1ULL << 32) | (unsigned)s[1023];
        atomicExch(&g_state[blockIdx.x], mine);
    }
    // parallel lookback: sum all predecessor aggregates (all 79 blocks resident)
    if (tid < 32) {
        int sum = 0;
        for (int j = tid; j < blockIdx.x; j += 32) {
            unsigned long long st;
            do { st = atomicAdd(&g_state[j], 0ULL); } while (!(st >> 32));
            sum += (int)(unsigned)st;
        }
#pragma unroll
        for (int o = 16; o > 0; o >>= 1) sum += __shfl_xor_sync(0xffffffffu, sum, o);
        if (tid == 0) s_prev = sum;
    }
    __syncthreads();
    int val = s[tid] + s_prev;
    if (i < NN) { g_off[i + 1] = val; g_cur[i + 1] = val; }
    if (i == 0) { g_off[0] = 0; g_cur[0] = 0; }
}

// ------------- launch 3: CSR fill -------------------------------------------
__global__ void k_fill(const int* __restrict__ row, const int* __restrict__ col) {
    int e = blockIdx.x * blockDim.x + threadIdx.x;
    if (e < NE) {
        int r = row[e];
        int p = atomicAdd(&g_cur[r], 1);
        g_col[p] = col[e];
    }
}

// ------------- fused layer: agg + 3 matvecs, 4 rows per warp ----------------
// W stored transposed in smem: Ws[m][(k<<5)+l] = (W[2l][k], W[2l+1][k])
__device__ __forceinline__ void mv4(const float2* __restrict__ Wm,
                                    const float2 v0, const float2 v1,
                                    const float2 v2, const float2 v3,
                                    float2& o0, float2& o1, float2& o2, float2& o3,
                                    int lane) {
    float2 a0 = {0.f, 0.f}, a1 = {0.f, 0.f}, a2 = {0.f, 0.f}, a3 = {0.f, 0.f};
#pragma unroll
    for (int k = 0; k < 64; k++) {
        float2 w = Wm[(k << 5) + lane];
        int srcl = k >> 1;
        float s0 = __shfl_sync(0xffffffffu, (k & 1) ? v0.y : v0.x, srcl);
        float s1 = __shfl_sync(0xffffffffu, (k & 1) ? v1.y : v1.x, srcl);
        float s2 = __shfl_sync(0xffffffffu, (k & 1) ? v2.y : v2.x, srcl);
        float s3 = __shfl_sync(0xffffffffu, (k & 1) ? v3.y : v3.x, srcl);
        a0.x = fmaf(s0, w.x, a0.x); a0.y = fmaf(s0, w.y, a0.y);
        a1.x = fmaf(s1, w.x, a1.x); a1.y = fmaf(s1, w.y, a1.y);
        a2.x = fmaf(s2, w.x, a2.x); a2.y = fmaf(s2, w.y, a2.y);
        a3.x = fmaf(s3, w.x, a3.x); a3.y = fmaf(s3, w.y, a3.y);
    }
    o0 = a0; o1 = a1; o2 = a2; o3 = a3;
}

__device__ __forceinline__ float2 agg_row(const float2* __restrict__ xin,
                                          int beg, int end, int lane) {
    float2 s0 = {0.f, 0.f}, s1 = {0.f, 0.f};
    int e = beg;
    for (; e + 4 <= end; e += 4) {
        int c0 = g_col[e], c1 = g_col[e + 1], c2 = g_col[e + 2], c3 = g_col[e + 3];
        float2 u0 = xin[c0 * 32 + lane];
        float2 u1 = xin[c1 * 32 + lane];
        float2 u2 = xin[c2 * 32 + lane];
        float2 u3 = xin[c3 * 32 + lane];
        s0.x += u0.x + u1.x; s0.y += u0.y + u1.y;
        s1.x += u2.x + u3.x; s1.y += u2.y + u3.y;
    }
    for (; e < end; e++) {
        int c = g_col[e];
        float2 u = xin[c * 32 + lane];
        s0.x += u.x; s0.y += u.y;
    }
    float invd = __fdividef(1.0f, (float)(end - beg));
    return make_float2((s0.x + s1.x) * invd, (s0.y + s1.y) * invd);
}

__global__ void __launch_bounds__(256)
k_layer(const float4* __restrict__ xin4, float4* __restrict__ xout4,
        const float* __restrict__ Wv, const float* __restrict__ Bv,
        const float* __restrict__ Wt, const float* __restrict__ Bt,
        const float* __restrict__ id_emb) {
    __shared__ float2 Ws[3 * 2048];  // 48 KB
    int tower = blockIdx.y;
    const float* W = tower ? Wt : Wv;
    const float* B = tower ? Bt : Bv;
    int t = threadIdx.x;
#pragma unroll
    for (int m = 0; m < 3; m++) {
        const float* Wm = W + m * 4096;
        for (int idx = t; idx < 2048; idx += 256) {
            int l = idx & 31, k = idx >> 5;
            Ws[m * 2048 + k * 32 + l] =
                make_float2(Wm[(2 * l) * 64 + k], Wm[(2 * l + 1) * 64 + k]);
        }
    }
    __syncthreads();

    int lane = t & 31, warp = t >> 5;
    const float2* xin = (const float2*)xin4 + (size_t)tower * (NN * 32);
    float2* xout = (float2*)xout4 + (size_t)tower * (NN * 32);
    const float2* id2 = (const float2*)id_emb;

    float2 b0 = ((const float2*)B)[lane];
    float2 b1 = ((const float2*)(B + 64))[lane];
    float2 b2 = ((const float2*)(B + 128))[lane];
    const float2* W0 = Ws;
    const float2* W1 = Ws + 2048;
    const float2* W2 = Ws + 4096;

    int gw = blockIdx.x * 8 + warp;
    int stride = gridDim.x * 8 * 4;
    for (int r = gw * 4; r < NN; r += stride) {
        // rows r..r+3 (NN % 4 == 0, so full quad whenever r < NN)
        int o0 = g_off[r], o1 = g_off[r + 1], o2 = g_off[r + 2],
            o3 = g_off[r + 3], o4 = g_off[r + 4];
        float2 a0 = agg_row(xin, o0, o1, lane);
        float2 a1 = agg_row(xin, o1, o2, lane);
        float2 a2 = agg_row(xin, o2, o3, lane);
        float2 a3 = agg_row(xin, o3, o4, lane);

        float2 x0 = xin[(r + 0) * 32 + lane];
        float2 x1 = xin[(r + 1) * 32 + lane];
        float2 x2 = xin[(r + 2) * 32 + lane];
        float2 x3 = xin[(r + 3) * 32 + lane];

        float2 t0, t1, t2, t3;
        // xhat = leaky(x@W1^T + b1) + id
        mv4(W1, x0, x1, x2, x3, t0, t1, t2, t3, lane);
        float2 i0 = id2[(r + 0) * 32 + lane];
        float2 i1 = id2[(r + 1) * 32 + lane];
        float2 i2 = id2[(r + 2) * 32 + lane];
        float2 i3 = id2[(r + 3) * 32 + lane];
        float2 xh0 = {leaky(t0.x + b1.x) + i0.x, leaky(t0.y + b1.y) + i0.y};
        float2 xh1 = {leaky(t1.x + b1.x) + i1.x, leaky(t1.y + b1.y) + i1.y};
        float2 xh2 = {leaky(t2.x + b1.x) + i2.x, leaky(t2.y + b1.y) + i2.y};
        float2 xh3 = {leaky(t3.x + b1.x) + i3.x, leaky(t3.y + b1.y) + i3.y};

        // h = leaky(agg@W0^T + b0)
        mv4(W0, a0, a1, a2, a3, t0, t1, t2, t3, lane);
        float2 h0 = {leaky(t0.x + b0.x), leaky(t0.y + b0.y)};
        float2 h1 = {leaky(t1.x + b0.x), leaky(t1.y + b0.y)};
        float2 h2 = {leaky(t2.x + b0.x), leaky(t2.y + b0.y)};
        float2 h3 = {leaky(t3.x + b0.x), leaky(t3.y + b0.y)};

        // out = leaky(h@W2^T + b2 + xhat)
        mv4(W2, h0, h1, h2, h3, t0, t1, t2, t3, lane);
        xout[(r + 0) * 32 + lane] = make_float2(leaky(t0.x + b2.x + xh0.x), leaky(t0.y + b2.y + xh0.y));
        xout[(r + 1) * 32 + lane] = make_float2(leaky(t1.x + b2.x + xh1.x), leaky(t1.y + b2.y + xh1.y));
        xout[(r + 2) * 32 + lane] = make_float2(leaky(t2.x + b2.x + xh2.x), leaky(t2.y + b2.y + xh2.y));
        xout[(r + 3) * 32 + lane] = make_float2(leaky(t3.x + b2.x + xh3.x), leaky(t3.y + b2.y + xh3.y));
    }
}

// ------------- final combine -------------------------------------------------
__global__ void k_combine(float4* __restrict__ out) {
    int i = blockIdx.x * blockDim.x + threadIdx.x;
    if (i < NN * 16) {
        float4 a = g_bufA[i], b = g_bufA[NN * 16 + i];
        out[i] = make_float4(0.5f * (a.x + b.x), 0.5f * (a.y + b.y),
                             0.5f * (a.z + b.z), 0.5f * (a.w + b.w));
    }
}

// ------------- launch --------------------------------------------------------
extern "C" void kernel_launch(void* const* d_in, const int* in_sizes, int n_in,
                              void* d_out, int out_size) {
    const float* v_feat = (const float*)d_in[0];
    const float* t_feat = (const float*)d_in[1];
    const float* id_emb = (const float*)d_in[2];
    const float* v_pref = (const float*)d_in[3];
    const float* t_pref = (const float*)d_in[4];
    const float* v_W    = (const float*)d_in[5];
    const float* v_b    = (const float*)d_in[6];
    const float* t_W    = (const float*)d_in[7];
    const float* t_b    = (const float*)d_in[8];
    const int*   edges  = (const int*)d_in[9];
    const int* row = edges;
    const int* col = edges + NE;
    float4* out = (float4*)d_out;

    float4 *bufA, *bufB;
    cudaGetSymbolAddress((void**)&bufA, g_bufA);
    cudaGetSymbolAddress((void**)&bufB, g_bufB);
    void *degp, *statep;
    cudaGetSymbolAddress(&degp, g_deg);
    cudaGetSymbolAddress(&statep, g_state);

    // async memset nodes (not kernel launches)
    cudaMemsetAsync(degp, 0, NN * sizeof(int));
    cudaMemsetAsync(statep, 0, NB_SCAN * sizeof(unsigned long long));

    // kernel launch #1: normalize both towers + histogram
    k_init_hist<<<20000, 256>>>(v_pref, v_feat, t_pref, t_feat, row);
    // #2: single-kernel prefix scan
    k_scan<<<NB_SCAN, 1024>>>();
    // #3: CSR fill
    k_fill<<<(NE + 255) / 256, 256>>>(row, col);

    // #4, #5: fused GCN layers (both towers per launch), ping-pong A->B->A
    dim3 lgrid(296, 2);
    k_layer<<<lgrid, 256>>>(bufA, bufB, v_W, v_b, t_W, t_b, id_emb);
    k_layer<<<lgrid, 256>>>(bufB, bufA, v_W + 3 * 4096, v_b + 3 * 64,
                            t_W + 3 * 4096, t_b + 3 * 64, id_emb);

    // #6: combine
    k_combine<<<(NN * 16 + 255) / 256, 256>>>(out);
}

// round 4
// speedup vs baseline: 1.6358x; 1.2689x over previous
#include <cuda_runtime.h>

#define NU 50000
#define NN 80000
#define NE 1600000
#define NB_SCAN 79   // ceil(80000/1024)

// ---------------- scratch (device globals; no allocation allowed) ----------
__device__ int    g_deg[NN];
__device__ int    g_off[NN + 1];
__device__ int    g_cur[NN + 1];
__device__ unsigned long long g_state[NB_SCAN];
__device__ int    g_col[NE];
__device__ float4 g_bufA[2 * NN * 16];   // [tower][node][16 float4]
__device__ float4 g_bufB[2 * NN * 16];

__device__ __forceinline__ float leaky(float x) {
    return fmaxf(x, 0.01f * x);
}

// packed f32x2 fma / add (FFMA2 only reachable via PTX on sm_103a)
__device__ __forceinline__ float2 ffma2(float2 s, float2 w, float2 c) {
    unsigned long long rs = *reinterpret_cast<unsigned long long*>(&s);
    unsigned long long rw = *reinterpret_cast<unsigned long long*>(&w);
    unsigned long long rc = *reinterpret_cast<unsigned long long*>(&c);
    unsigned long long rd;
    asm("fma.rn.f32x2 %0, %1, %2, %3;" : "=l"(rd) : "l"(rs), "l"(rw), "l"(rc));
    return *reinterpret_cast<float2*>(&rd);
}
__device__ __forceinline__ float2 add2(float2 a, float2 b) {
    unsigned long long ra = *reinterpret_cast<unsigned long long*>(&a);
    unsigned long long rb = *reinterpret_cast<unsigned long long*>(&b);
    unsigned long long rd;
    asm("add.rn.f32x2 %0, %1, %2;" : "=l"(rd) : "l"(ra), "l"(rb));
    return *reinterpret_cast<float2*>(&rd);
}

// ------------- launch 1: normalize both towers + edge histogram -------------
__global__ void k_init_hist(const float* __restrict__ v_pref, const float* __restrict__ v_feat,
                            const float* __restrict__ t_pref, const float* __restrict__ t_feat,
                            const int* __restrict__ row) {
    int gid = blockIdx.x * blockDim.x + threadIdx.x;
    if (gid < NE) atomicAdd(&g_deg[row[gid]], 1);
    int w = gid >> 5;
    if (w >= 2 * NN) return;
    int lane = gid & 31;
    int tower = (w >= NN) ? 1 : 0;
    int n = w - tower * NN;
    const float2* src;
    if (tower == 0)
        src = (n < NU) ? (const float2*)v_pref + n * 32 : (const float2*)v_feat + (n - NU) * 32;
    else
        src = (n < NU) ? (const float2*)t_pref + n * 32 : (const float2*)t_feat + (n - NU) * 32;
    float2 v = src[lane];
    float ss = v.x * v.x + v.y * v.y;
#pragma unroll
    for (int o = 16; o > 0; o >>= 1) ss += __shfl_xor_sync(0xffffffffu, ss, o);
    float inv = 1.0f / fmaxf(sqrtf(ss), 1e-12f);
    ((float2*)g_bufA)[w * 32 + lane] = make_float2(v.x * inv, v.y * inv);
}

// ------------- launch 2: single-kernel scan (parallel lookback) -------------
__global__ void k_scan() {
    __shared__ int s[1024];
    __shared__ int s_prev;
    int tid = threadIdx.x;
    int i = blockIdx.x * 1024 + tid;
    int v = (i < NN) ? g_deg[i] : 0;
    s[tid] = v;
    __syncthreads();
#pragma unroll
    for (int off = 1; off < 1024; off <<= 1) {
        int t = (tid >= off) ? s[tid - off] : 0;
        __syncthreads();
        s[tid] += t;
        __syncthreads();
    }
    if (tid == 0) {
        unsigned long long mine = (1ULL << 32) | (unsigned)s[1023];
        atomicExch(&g_state[blockIdx.x], mine);
    }
    if (tid < 32) {
        int sum = 0;
        for (int j = tid; j < blockIdx.x; j += 32) {
            unsigned long long st;
            do { st = atomicAdd(&g_state[j], 0ULL); } while (!(st >> 32));
            sum += (int)(unsigned)st;
        }
#pragma unroll
        for (int o = 16; o > 0; o >>= 1) sum += __shfl_xor_sync(0xffffffffu, sum, o);
        if (tid == 0) s_prev = sum;
    }
    __syncthreads();
    int val = s[tid] + s_prev;
    if (i < NN) { g_off[i + 1] = val; g_cur[i + 1] = val; }
    if (i == 0) { g_off[0] = 0; g_cur[0] = 0; }
}

// ------------- launch 3: CSR fill -------------------------------------------
__global__ void k_fill(const int* __restrict__ row, const int* __restrict__ col) {
    int e = blockIdx.x * blockDim.x + threadIdx.x;
    if (e < NE) {
        int r = row[e];
        int p = atomicAdd(&g_cur[r], 1);
        g_col[p] = col[e];
    }
}

// ------------- fused layer ---------------------------------------------------
// Weights in smem as float4:  Ws4[m][k2*32 + l] = (W[2l][2k2], W[2l+1][2k2],
//                                                  W[2l][2k2+1], W[2l+1][2k2+1])
// Row staging (per warp, duplicated pairs): stg[r*32 + k2] = (x[2k2],x[2k2],
//                                                             x[2k2+1],x[2k2+1])
// lane l accumulates outputs (2l, 2l+1): accA = even-k partials, accB = odd-k.

__device__ __forceinline__ void stage4(float4* __restrict__ stg, int lane,
                                       float2 v0, float2 v1, float2 v2, float2 v3) {
    __syncwarp();
    stg[0 * 32 + lane] = make_float4(v0.x, v0.x, v0.y, v0.y);
    stg[1 * 32 + lane] = make_float4(v1.x, v1.x, v1.y, v1.y);
    stg[2 * 32 + lane] = make_float4(v2.x, v2.x, v2.y, v2.y);
    stg[3 * 32 + lane] = make_float4(v3.x, v3.x, v3.y, v3.y);
    __syncwarp();
}

__device__ __forceinline__ void mv4s(const float4* __restrict__ Wm,
                                     const float4* __restrict__ stg,
                                     float2& o0, float2& o1, float2& o2, float2& o3,
                                     int lane) {
    float2 a0A = {0.f, 0.f}, a0B = {0.f, 0.f};
    float2 a1A = {0.f, 0.f}, a1B = {0.f, 0.f};
    float2 a2A = {0.f, 0.f}, a2B = {0.f, 0.f};
    float2 a3A = {0.f, 0.f}, a3B = {0.f, 0.f};
#pragma unroll
    for (int k2 = 0; k2 < 32; k2++) {
        float4 w = Wm[(k2 << 5) + lane];
        float2 wlo = make_float2(w.x, w.y);
        float2 whi = make_float2(w.z, w.w);
        float4 s0 = stg[0 * 32 + k2];
        float4 s1 = stg[1 * 32 + k2];
        float4 s2 = stg[2 * 32 + k2];
        float4 s3 = stg[3 * 32 + k2];
        a0A = ffma2(make_float2(s0.x, s0.y), wlo, a0A);
        a0B = ffma2(make_float2(s0.z, s0.w), whi, a0B);
        a1A = ffma2(make_float2(s1.x, s1.y), wlo, a1A);
        a1B = ffma2(make_float2(s1.z, s1.w), whi, a1B);
        a2A = ffma2(make_float2(s2.x, s2.y), wlo, a2A);
        a2B = ffma2(make_float2(s2.z, s2.w), whi, a2B);
        a3A = ffma2(make_float2(s3.x, s3.y), wlo, a3A);
        a3B = ffma2(make_float2(s3.z, s3.w), whi, a3B);
    }
    o0 = add2(a0A, a0B);
    o1 = add2(a1A, a1B);
    o2 = add2(a2A, a2B);
    o3 = add2(a3A, a3B);
}

__device__ __forceinline__ float2 agg_row(const float2* __restrict__ xin,
                                          int beg, int end, int lane) {
    float2 s0 = {0.f, 0.f}, s1 = {0.f, 0.f};
    int e = beg;
    for (; e + 4 <= end; e += 4) {
        int c0 = g_col[e], c1 = g_col[e + 1], c2 = g_col[e + 2], c3 = g_col[e + 3];
        float2 u0 = xin[c0 * 32 + lane];
        float2 u1 = xin[c1 * 32 + lane];
        float2 u2 = xin[c2 * 32 + lane];
        float2 u3 = xin[c3 * 32 + lane];
        s0 = add2(s0, add2(u0, u1));
        s1 = add2(s1, add2(u2, u3));
    }
    for (; e < end; e++) {
        int c = g_col[e];
        s0 = add2(s0, xin[c * 32 + lane]);
    }
    float invd = __fdividef(1.0f, (float)(end - beg));
    float2 s = add2(s0, s1);
    return make_float2(s.x * invd, s.y * invd);
}

__global__ void __launch_bounds__(256, 3)
k_layer(const float4* __restrict__ xin4, float4* __restrict__ xout4,
        const float* __restrict__ Wv, const float* __restrict__ Bv,
        const float* __restrict__ Wt, const float* __restrict__ Bt,
        const float* __restrict__ id_emb) {
    extern __shared__ float4 sdyn[];        // 3072 weights + 8*128 staging
    float4* Ws4 = sdyn;                     // 48 KB
    int tower = blockIdx.y;
    const float* W = tower ? Wt : Wv;
    const float* B = tower ? Bt : Bv;
    int t = threadIdx.x;
    for (int idx = t; idx < 3072; idx += 256) {
        int m = idx >> 10, rem = idx & 1023;
        int k2 = rem >> 5, l = rem & 31;
        const float* Wm = W + m * 4096;
        Ws4[idx] = make_float4(Wm[(2 * l) * 64 + 2 * k2],
                               Wm[(2 * l + 1) * 64 + 2 * k2],
                               Wm[(2 * l) * 64 + 2 * k2 + 1],
                               Wm[(2 * l + 1) * 64 + 2 * k2 + 1]);
    }
    __syncthreads();

    int lane = t & 31, warp = t >> 5;
    float4* stg = sdyn + 3072 + warp * 128;  // 4 rows x 32 float4 per warp

    const float2* xin = (const float2*)xin4 + (size_t)tower * (NN * 32);
    float2* xout = (float2*)xout4 + (size_t)tower * (NN * 32);
    const float2* id2 = (const float2*)id_emb;

    float2 b0 = ((const float2*)B)[lane];
    float2 b1 = ((const float2*)(B + 64))[lane];
    float2 b2 = ((const float2*)(B + 128))[lane];
    const float4* W0 = Ws4;
    const float4* W1 = Ws4 + 1024;
    const float4* W2 = Ws4 + 2048;

    int gw = blockIdx.x * 8 + warp;
    int stride = gridDim.x * 8 * 4;
    for (int r = gw * 4; r < NN; r += stride) {
        int o0 = g_off[r], o1 = g_off[r + 1], o2 = g_off[r + 2],
            o3 = g_off[r + 3], o4 = g_off[r + 4];
        float2 a0 = agg_row(xin, o0, o1, lane);
        float2 a1 = agg_row(xin, o1, o2, lane);
        float2 a2 = agg_row(xin, o2, o3, lane);
        float2 a3 = agg_row(xin, o3, o4, lane);

        float2 x0 = xin[(r + 0) * 32 + lane];
        float2 x1 = xin[(r + 1) * 32 + lane];
        float2 x2 = xin[(r + 2) * 32 + lane];
        float2 x3 = xin[(r + 3) * 32 + lane];

        float2 t0, t1, t2, t3;
        // xhat = leaky(x@W1^T + b1) + id
        stage4(stg, lane, x0, x1, x2, x3);
        mv4s(W1, stg, t0, t1, t2, t3, lane);
        float2 i0 = id2[(r + 0) * 32 + lane];
        float2 i1 = id2[(r + 1) * 32 + lane];
        float2 i2 = id2[(r + 2) * 32 + lane];
        float2 i3 = id2[(r + 3) * 32 + lane];
        float2 xh0 = {leaky(t0.x + b1.x) + i0.x, leaky(t0.y + b1.y) + i0.y};
        float2 xh1 = {leaky(t1.x + b1.x) + i1.x, leaky(t1.y + b1.y) + i1.y};
        float2 xh2 = {leaky(t2.x + b1.x) + i2.x, leaky(t2.y + b1.y) + i2.y};
        float2 xh3 = {leaky(t3.x + b1.x) + i3.x, leaky(t3.y + b1.y) + i3.y};

        // h = leaky(agg@W0^T + b0)
        stage4(stg, lane, a0, a1, a2, a3);
        mv4s(W0, stg, t0, t1, t2, t3, lane);
        float2 h0 = {leaky(t0.x + b0.x), leaky(t0.y + b0.y)};
        float2 h1 = {leaky(t1.x + b0.x), leaky(t1.y + b0.y)};
        float2 h2 = {leaky(t2.x + b0.x), leaky(t2.y + b0.y)};
        float2 h3 = {leaky(t3.x + b0.x), leaky(t3.y + b0.y)};

        // out = leaky(h@W2^T + b2 + xhat)
        stage4(stg, lane, h0, h1, h2, h3);
        mv4s(W2, stg, t0, t1, t2, t3, lane);
        xout[(r + 0) * 32 + lane] = make_float2(leaky(t0.x + b2.x + xh0.x), leaky(t0.y + b2.y + xh0.y));
        xout[(r + 1) * 32 + lane] = make_float2(leaky(t1.x + b2.x + xh1.x), leaky(t1.y + b2.y + xh1.y));
        xout[(r + 2) * 32 + lane] = make_float2(leaky(t2.x + b2.x + xh2.x), leaky(t2.y + b2.y + xh2.y));
        xout[(r + 3) * 32 + lane] = make_float2(leaky(t3.x + b2.x + xh3.x), leaky(t3.y + b2.y + xh3.y));
    }
}

// ------------- final combine -------------------------------------------------
__global__ void k_combine(float4* __restrict__ out) {
    int i = blockIdx.x * blockDim.x + threadIdx.x;
    if (i < NN * 16) {
        float4 a = g_bufA[i], b = g_bufA[NN * 16 + i];
        out[i] = make_float4(0.5f * (a.x + b.x), 0.5f * (a.y + b.y),
                             0.5f * (a.z + b.z), 0.5f * (a.w + b.w));
    }
}

// ------------- launch --------------------------------------------------------
extern "C" void kernel_launch(void* const* d_in, const int* in_sizes, int n_in,
                              void* d_out, int out_size) {
    const float* v_feat = (const float*)d_in[0];
    const float* t_feat = (const float*)d_in[1];
    const float* id_emb = (const float*)d_in[2];
    const float* v_pref = (const float*)d_in[3];
    const float* t_pref = (const float*)d_in[4];
    const float* v_W    = (const float*)d_in[5];
    const float* v_b    = (const float*)d_in[6];
    const float* t_W    = (const float*)d_in[7];
    const float* t_b    = (const float*)d_in[8];
    const int*   edges  = (const int*)d_in[9];
    const int* row = edges;
    const int* col = edges + NE;
    float4* out = (float4*)d_out;

    float4 *bufA, *bufB;
    cudaGetSymbolAddress((void**)&bufA, g_bufA);
    cudaGetSymbolAddress((void**)&bufB, g_bufB);
    void *degp, *statep;
    cudaGetSymbolAddress(&degp, g_deg);
    cudaGetSymbolAddress(&statep, g_state);

    const int LAYER_SMEM = (3072 + 8 * 128) * sizeof(float4);  // 64 KB
    static int attr_done = 0;
    if (!attr_done) {
        cudaFuncSetAttribute(k_layer, cudaFuncAttributeMaxDynamicSharedMemorySize, LAYER_SMEM);
        attr_done = 1;
    }

    cudaMemsetAsync(degp, 0, NN * sizeof(int));
    cudaMemsetAsync(statep, 0, NB_SCAN * sizeof(unsigned long long));

    k_init_hist<<<20000, 256>>>(v_pref, v_feat, t_pref, t_feat, row);
    k_scan<<<NB_SCAN, 1024>>>();
    k_fill<<<(NE + 255) / 256, 256>>>(row, col);

    // fused GCN layers (both towers per launch), one full wave: 222x2 = 444 blocks
    dim3 lgrid(222, 2);
    k_layer<<<lgrid, 256, LAYER_SMEM>>>(bufA, bufB, v_W, v_b, t_W, t_b, id_emb);
    k_layer<<<lgrid, 256, LAYER_SMEM>>>(bufB, bufA, v_W + 3 * 4096, v_b + 3 * 64,
                                        t_W + 3 * 4096, t_b + 3 * 64, id_emb);

    k_combine<<<(NN * 16 + 255) / 256, 256>>>(out);
}

// round 5
// speedup vs baseline: 1.8026x; 1.1019x over previous
#include <cuda_runtime.h>

#define NU 50000
#define NN 80000
#define NE 1600000
#define NB_SCAN 79   // ceil(80000/1024)

// ---------------- scratch (device globals; no allocation allowed) ----------
__device__ int    g_deg[NN];
__device__ int    g_off[NN + 1];
__device__ int    g_cur[NN + 1];
__device__ unsigned long long g_state[NB_SCAN];
__device__ int    g_col[NE];
__device__ float4 g_bufA[2 * NN * 16];   // [tower][node][16 float4]
__device__ float4 g_bufB[2 * NN * 16];

__device__ __forceinline__ float leaky(float x) {
    return fmaxf(x, 0.01f * x);
}

// packed f32x2 fma / add (FFMA2 only reachable via PTX on sm_103a)
__device__ __forceinline__ float2 ffma2(float2 s, float2 w, float2 c) {
    unsigned long long rs = *reinterpret_cast<unsigned long long*>(&s);
    unsigned long long rw = *reinterpret_cast<unsigned long long*>(&w);
    unsigned long long rc = *reinterpret_cast<unsigned long long*>(&c);
    unsigned long long rd;
    asm("fma.rn.f32x2 %0, %1, %2, %3;" : "=l"(rd) : "l"(rs), "l"(rw), "l"(rc));
    return *reinterpret_cast<float2*>(&rd);
}
__device__ __forceinline__ float2 add2(float2 a, float2 b) {
    unsigned long long ra = *reinterpret_cast<unsigned long long*>(&a);
    unsigned long long rb = *reinterpret_cast<unsigned long long*>(&b);
    unsigned long long rd;
    asm("add.rn.f32x2 %0, %1, %2;" : "=l"(rd) : "l"(ra), "l"(rb));
    return *reinterpret_cast<float2*>(&rd);
}

// ------------- launch 1: normalize both towers + edge histogram -------------
__global__ void k_init_hist(const float* __restrict__ v_pref, const float* __restrict__ v_feat,
                            const float* __restrict__ t_pref, const float* __restrict__ t_feat,
                            const int* __restrict__ row) {
    int gid = blockIdx.x * blockDim.x + threadIdx.x;
    if (gid < NE) atomicAdd(&g_deg[row[gid]], 1);
    int w = gid >> 5;
    if (w >= 2 * NN) return;
    int lane = gid & 31;
    int tower = (w >= NN) ? 1 : 0;
    int n = w - tower * NN;
    const float2* src;
    if (tower == 0)
        src = (n < NU) ? (const float2*)v_pref + n * 32 : (const float2*)v_feat + (n - NU) * 32;
    else
        src = (n < NU) ? (const float2*)t_pref + n * 32 : (const float2*)t_feat + (n - NU) * 32;
    float2 v = src[lane];
    float ss = v.x * v.x + v.y * v.y;
#pragma unroll
    for (int o = 16; o > 0; o >>= 1) ss += __shfl_xor_sync(0xffffffffu, ss, o);
    float inv = 1.0f / fmaxf(sqrtf(ss), 1e-12f);
    ((float2*)g_bufA)[w * 32 + lane] = make_float2(v.x * inv, v.y * inv);
}

// ------------- launch 2: single-kernel scan (parallel lookback) -------------
__global__ void k_scan() {
    __shared__ int s[1024];
    __shared__ int s_prev;
    int tid = threadIdx.x;
    int i = blockIdx.x * 1024 + tid;
    int v = (i < NN) ? g_deg[i] : 0;
    s[tid] = v;
    __syncthreads();
#pragma unroll
    for (int off = 1; off < 1024; off <<= 1) {
        int t = (tid >= off) ? s[tid - off] : 0;
        __syncthreads();
        s[tid] += t;
        __syncthreads();
    }
    if (tid == 0) {
        unsigned long long mine = (1ULL << 32) | (unsigned)s[1023];
        atomicExch(&g_state[blockIdx.x], mine);
    }
    if (tid < 32) {
        int sum = 0;
        for (int j = tid; j < blockIdx.x; j += 32) {
            unsigned long long st;
            do { st = atomicAdd(&g_state[j], 0ULL); } while (!(st >> 32));
            sum += (int)(unsigned)st;
        }
#pragma unroll
        for (int o = 16; o > 0; o >>= 1) sum += __shfl_xor_sync(0xffffffffu, sum, o);
        if (tid == 0) s_prev = sum;
    }
    __syncthreads();
    int val = s[tid] + s_prev;
    if (i < NN) { g_off[i + 1] = val; g_cur[i + 1] = val; }
    if (i == 0) { g_off[0] = 0; g_cur[0] = 0; }
}

// ------------- launch 3: CSR fill -------------------------------------------
__global__ void k_fill(const int* __restrict__ row, const int* __restrict__ col) {
    int e = blockIdx.x * blockDim.x + threadIdx.x;
    if (e < NE) {
        int r = row[e];
        int p = atomicAdd(&g_cur[r], 1);
        g_col[p] = col[e];
    }
}

// ------------- fused layer, 8 rows per warp ----------------------------------
// Weight smem layout (per matrix m, per k4 in [0,16), per j in {0,1}, lane l):
//   Ws4[m*1024 + k4*64 + j*32 + l] = (W[2l+j][4k4], W[2l+j][4k4+1],
//                                     W[2l+j][4k4+2], W[2l+j][4k4+3])
// -> each weight LDS.128 is 512B fully coalesced, conflict-free.
// Staging: per warp, 8 rows stored as raw float2 per lane (stg2[r*32+l] = (x[2l],x[2l+1]));
// read back as float4 broadcast (x[4k4..4k4+3]).
// Lane l accumulates outputs (2l, 2l+1); acc float2 = (even-k partial, odd-k partial).

#define RB 8

__device__ __forceinline__ void stage8(float2* __restrict__ stg2, int lane,
                                       const float2* v) {
    __syncwarp();
#pragma unroll
    for (int r = 0; r < RB; r++) stg2[r * 32 + lane] = v[r];
    __syncwarp();
}

__device__ __forceinline__ void mv8(const float4* __restrict__ Wm4,
                                    const float4* __restrict__ stg4,
                                    float2* __restrict__ out, int lane) {
    float2 acc0[RB], acc1[RB];
#pragma unroll
    for (int r = 0; r < RB; r++) {
        acc0[r] = make_float2(0.f, 0.f);
        acc1[r] = make_float2(0.f, 0.f);
    }
#pragma unroll
    for (int k4 = 0; k4 < 16; k4++) {
        float4 w0 = Wm4[(k4 << 6) + lane];        // W[2l][4k4..+3]
        float4 w1 = Wm4[(k4 << 6) + 32 + lane];   // W[2l+1][4k4..+3]
        float2 w0lo = make_float2(w0.x, w0.y), w0hi = make_float2(w0.z, w0.w);
        float2 w1lo = make_float2(w1.x, w1.y), w1hi = make_float2(w1.z, w1.w);
#pragma unroll
        for (int r = 0; r < RB; r++) {
            float4 s = stg4[r * 16 + k4];         // broadcast
            float2 slo = make_float2(s.x, s.y), shi = make_float2(s.z, s.w);
            acc0[r] = ffma2(slo, w0lo, acc0[r]);
            acc0[r] = ffma2(shi, w0hi, acc0[r]);
            acc1[r] = ffma2(slo, w1lo, acc1[r]);
            acc1[r] = ffma2(shi, w1hi, acc1[r]);
        }
    }
#pragma unroll
    for (int r = 0; r < RB; r++)
        out[r] = make_float2(acc0[r].x + acc0[r].y, acc1[r].x + acc1[r].y);
}

__device__ __forceinline__ float2 agg_row(const float2* __restrict__ xin,
                                          int beg, int end, int lane) {
    float2 s0 = {0.f, 0.f}, s1 = {0.f, 0.f};
    int e = beg;
    for (; e + 4 <= end; e += 4) {
        int c0 = g_col[e], c1 = g_col[e + 1], c2 = g_col[e + 2], c3 = g_col[e + 3];
        float2 u0 = xin[c0 * 32 + lane];
        float2 u1 = xin[c1 * 32 + lane];
        float2 u2 = xin[c2 * 32 + lane];
        float2 u3 = xin[c3 * 32 + lane];
        s0 = add2(s0, add2(u0, u1));
        s1 = add2(s1, add2(u2, u3));
    }
    for (; e < end; e++) {
        int c = g_col[e];
        s0 = add2(s0, xin[c * 32 + lane]);
    }
    float invd = __fdividef(1.0f, (float)(end - beg));
    float2 s = add2(s0, s1);
    return make_float2(s.x * invd, s.y * invd);
}

__global__ void __launch_bounds__(256, 2)
k_layer(const float4* __restrict__ xin4, float4* __restrict__ xout4,
        const float* __restrict__ Wv, const float* __restrict__ Bv,
        const float* __restrict__ Wt, const float* __restrict__ Bt,
        const float* __restrict__ id_emb) {
    extern __shared__ float4 sdyn[];   // 3072 weight float4 + 8 warps * 128 staging float4
    float4* Ws4 = sdyn;                // 48 KB
    int tower = blockIdx.y;
    const float* W = tower ? Wt : Wv;
    const float* B = tower ? Bt : Bv;
    int t = threadIdx.x;
    for (int idx = t; idx < 3072; idx += 256) {
        int m = idx >> 10, rem = idx & 1023;
        int k4 = rem >> 6, j = (rem >> 5) & 1, l = rem & 31;
        const float4* gW4 = (const float4*)(W + m * 4096);
        Ws4[idx] = gW4[(2 * l + j) * 16 + k4];
    }
    __syncthreads();

    int lane = t & 31, warp = t >> 5;
    float4* stg4 = sdyn + 3072 + warp * 128;   // 8 rows x 16 float4 per warp
    float2* stg2 = (float2*)stg4;

    const float2* xin = (const float2*)xin4 + (size_t)tower * (NN * 32);
    float2* xout = (float2*)xout4 + (size_t)tower * (NN * 32);
    const float2* id2 = (const float2*)id_emb;

    float2 b0 = ((const float2*)B)[lane];
    float2 b1 = ((const float2*)(B + 64))[lane];
    float2 b2 = ((const float2*)(B + 128))[lane];
    const float4* W0 = Ws4;
    const float4* W1 = Ws4 + 1024;
    const float4* W2 = Ws4 + 2048;

    int gw = blockIdx.x * 8 + warp;
    int stride = gridDim.x * 8 * RB;
    for (int r = gw * RB; r < NN; r += stride) {
        int off[RB + 1];
#pragma unroll
        for (int q = 0; q <= RB; q++) off[q] = g_off[r + q];

        // aggregate 8 rows
        float2 a[RB];
#pragma unroll
        for (int q = 0; q < RB; q++) a[q] = agg_row(xin, off[q], off[q + 1], lane);

        // xhat = leaky(x@W1^T + b1) + id
        float2 x[RB], tmp[RB], xh[RB];
#pragma unroll
        for (int q = 0; q < RB; q++) x[q] = xin[(r + q) * 32 + lane];
        stage8(stg2, lane, x);
        mv8(W1, stg4, tmp, lane);
#pragma unroll
        for (int q = 0; q < RB; q++) {
            float2 idv = id2[(r + q) * 32 + lane];
            xh[q] = make_float2(leaky(tmp[q].x + b1.x) + idv.x,
                                leaky(tmp[q].y + b1.y) + idv.y);
        }

        // h = leaky(agg@W0^T + b0)
        stage8(stg2, lane, a);
        mv8(W0, stg4, tmp, lane);
        float2 h[RB];
#pragma unroll
        for (int q = 0; q < RB; q++)
            h[q] = make_float2(leaky(tmp[q].x + b0.x), leaky(tmp[q].y + b0.y));

        // out = leaky(h@W2^T + b2 + xhat)
        stage8(stg2, lane, h);
        mv8(W2, stg4, tmp, lane);
#pragma unroll
        for (int q = 0; q < RB; q++)
            xout[(r + q) * 32 + lane] =
                make_float2(leaky(tmp[q].x + b2.x + xh[q].x),
                            leaky(tmp[q].y + b2.y + xh[q].y));
    }
}

// ------------- final combine -------------------------------------------------
__global__ void k_combine(float4* __restrict__ out) {
    int i = blockIdx.x * blockDim.x + threadIdx.x;
    if (i < NN * 16) {
        float4 a = g_bufA[i], b = g_bufA[NN * 16 + i];
        out[i] = make_float4(0.5f * (a.x + b.x), 0.5f * (a.y + b.y),
                             0.5f * (a.z + b.z), 0.5f * (a.w + b.w));
    }
}

// ------------- launch --------------------------------------------------------
extern "C" void kernel_launch(void* const* d_in, const int* in_sizes, int n_in,
                              void* d_out, int out_size) {
    const float* v_feat = (const float*)d_in[0];
    const float* t_feat = (const float*)d_in[1];
    const float* id_emb = (const float*)d_in[2];
    const float* v_pref = (const float*)d_in[3];
    const float* t_pref = (const float*)d_in[4];
    const float* v_W    = (const float*)d_in[5];
    const float* v_b    = (const float*)d_in[6];
    const float* t_W    = (const float*)d_in[7];
    const float* t_b    = (const float*)d_in[8];
    const int*   edges  = (const int*)d_in[9];
    const int* row = edges;
    const int* col = edges + NE;
    float4* out = (float4*)d_out;

    float4 *bufA, *bufB;
    cudaGetSymbolAddress((void**)&bufA, g_bufA);
    cudaGetSymbolAddress((void**)&bufB, g_bufB);
    void *degp, *statep;
    cudaGetSymbolAddress(&degp, g_deg);
    cudaGetSymbolAddress(&statep, g_state);

    const int LAYER_SMEM = (3072 + 8 * 128) * sizeof(float4);  // 64 KB
    static int attr_done = 0;
    if (!attr_done) {
        cudaFuncSetAttribute(k_layer, cudaFuncAttributeMaxDynamicSharedMemorySize, LAYER_SMEM);
        attr_done = 1;
    }

    cudaMemsetAsync(degp, 0, NN * sizeof(int));
    cudaMemsetAsync(statep, 0, NB_SCAN * sizeof(unsigned long long));

    k_init_hist<<<20000, 256>>>(v_pref, v_feat, t_pref, t_feat, row);
    k_scan<<<NB_SCAN, 1024>>>();
    k_fill<<<(NE + 255) / 256, 256>>>(row, col);

    // fused GCN layers (both towers per launch), 2 blocks/SM = one wave: 148x2
    dim3 lgrid(148, 2);
    k_layer<<<lgrid, 256, LAYER_SMEM>>>(bufA, bufB, v_W, v_b, t_W, t_b, id_emb);
    k_layer<<<lgrid, 256, LAYER_SMEM>>>(bufB, bufA, v_W + 3 * 4096, v_b + 3 * 64,
                                        t_W + 3 * 4096, t_b + 3 * 64, id_emb);

    k_combine<<<(NN * 16 + 255) / 256, 256>>>(out);
}

// round 6
// speedup vs baseline: 2.4120x; 1.3381x over previous
#include <cuda_runtime.h>
#include <cuda_fp16.h>

#define NU 50000
#define NN 80000
#define NE 1600000
#define NB_SCAN 79   // ceil(80000/1024)

// ---------------- scratch (device globals; no allocation allowed) ----------
__device__ int    g_deg[NN];
__device__ int    g_off[NN + 1];
__device__ int    g_cur[NN + 1];
__device__ unsigned long long g_state[NB_SCAN];
__device__ int    g_col[NE];
__device__ __half2 g_x[2 * NN * 32];     // [tower][node][32 half2] = 20.5 MB
__device__ __half2 g_agg[2 * NN * 32];
__device__ __half2 g_idh[NN * 32];

__device__ __forceinline__ float leaky(float x) {
    return fmaxf(x, 0.01f * x);
}

// packed f32x2 fma / add (FFMA2 only reachable via PTX on sm_103a)
__device__ __forceinline__ float2 ffma2(float2 s, float2 w, float2 c) {
    unsigned long long rs = *reinterpret_cast<unsigned long long*>(&s);
    unsigned long long rw = *reinterpret_cast<unsigned long long*>(&w);
    unsigned long long rc = *reinterpret_cast<unsigned long long*>(&c);
    unsigned long long rd;
    asm("fma.rn.f32x2 %0, %1, %2, %3;" : "=l"(rd) : "l"(rs), "l"(rw), "l"(rc));
    return *reinterpret_cast<float2*>(&rd);
}
__device__ __forceinline__ float2 add2(float2 a, float2 b) {
    unsigned long long ra = *reinterpret_cast<unsigned long long*>(&a);
    unsigned long long rb = *reinterpret_cast<unsigned long long*>(&b);
    unsigned long long rd;
    asm("add.rn.f32x2 %0, %1, %2;" : "=l"(rd) : "l"(ra), "l"(rb));
    return *reinterpret_cast<float2*>(&rd);
}

// ------------- launch 1: normalize + id->half + edge histogram --------------
__global__ void k_init_hist(const float* __restrict__ v_pref, const float* __restrict__ v_feat,
                            const float* __restrict__ t_pref, const float* __restrict__ t_feat,
                            const float* __restrict__ id_emb,
                            const int* __restrict__ row) {
    int gid = blockIdx.x * blockDim.x + threadIdx.x;
    if (gid < NE) atomicAdd(&g_deg[row[gid]], 1);
    int w = gid >> 5;
    int lane = gid & 31;
    if (w < NN) {
        float2 iv = ((const float2*)id_emb)[w * 32 + lane];
        g_idh[w * 32 + lane] = __float22half2_rn(iv);
    }
    if (w >= 2 * NN) return;
    int tower = (w >= NN) ? 1 : 0;
    int n = w - tower * NN;
    const float2* src;
    if (tower == 0)
        src = (n < NU) ? (const float2*)v_pref + n * 32 : (const float2*)v_feat + (n - NU) * 32;
    else
        src = (n < NU) ? (const float2*)t_pref + n * 32 : (const float2*)t_feat + (n - NU) * 32;
    float2 v = src[lane];
    float ss = v.x * v.x + v.y * v.y;
#pragma unroll
    for (int o = 16; o > 0; o >>= 1) ss += __shfl_xor_sync(0xffffffffu, ss, o);
    float inv = 1.0f / fmaxf(sqrtf(ss), 1e-12f);
    g_x[w * 32 + lane] = __float22half2_rn(make_float2(v.x * inv, v.y * inv));
}

// ------------- launch 2: single-kernel scan (parallel lookback) -------------
__global__ void k_scan() {
    __shared__ int s[1024];
    __shared__ int s_prev;
    int tid = threadIdx.x;
    int i = blockIdx.x * 1024 + tid;
    int v = (i < NN) ? g_deg[i] : 0;
    s[tid] = v;
    __syncthreads();
#pragma unroll
    for (int off = 1; off < 1024; off <<= 1) {
        int t = (tid >= off) ? s[tid - off] : 0;
        __syncthreads();
        s[tid] += t;
        __syncthreads();
    }
    if (tid == 0) {
        unsigned long long mine = (1ULL << 32) | (unsigned)s[1023];
        atomicExch(&g_state[blockIdx.x], mine);
    }
    if (tid < 32) {
        int sum = 0;
        for (int j = tid; j < blockIdx.x; j += 32) {
            unsigned long long st;
            do { st = atomicAdd(&g_state[j], 0ULL); } while (!(st >> 32));
            sum += (int)(unsigned)st;
        }
#pragma unroll
        for (int o = 16; o > 0; o >>= 1) sum += __shfl_xor_sync(0xffffffffu, sum, o);
        if (tid == 0) s_prev = sum;
    }
    __syncthreads();
    int val = s[tid] + s_prev;
    if (i < NN) { g_off[i + 1] = val; g_cur[i + 1] = val; }
    if (i == 0) { g_off[0] = 0; g_cur[0] = 0; }
}

// ------------- launch 3: CSR fill -------------------------------------------
__global__ void k_fill(const int* __restrict__ row, const int* __restrict__ col) {
    int e = blockIdx.x * blockDim.x + threadIdx.x;
    if (e < NE) {
        int r = row[e];
        int p = atomicAdd(&g_cur[r], 1);
        g_col[p] = col[e];
    }
}

// ------------- aggregation kernel: warp per row-tower, half2 gather ----------
__global__ void __launch_bounds__(512)
k_agg() {
    int gw = (blockIdx.x * 512 + threadIdx.x) >> 5;
    if (gw >= 2 * NN) return;
    int lane = threadIdx.x & 31;
    int tower = (gw >= NN) ? 1 : 0;
    int r = gw - tower * NN;
    const __half2* __restrict__ xin = g_x + (size_t)tower * (NN * 32);
    int beg = g_off[r], end = g_off[r + 1];
    float2 s0 = {0.f, 0.f}, s1 = {0.f, 0.f};
    int e = beg;
    for (; e + 4 <= end; e += 4) {
        int c0 = g_col[e], c1 = g_col[e + 1], c2 = g_col[e + 2], c3 = g_col[e + 3];
        float2 u0 = __half22float2(xin[c0 * 32 + lane]);
        float2 u1 = __half22float2(xin[c1 * 32 + lane]);
        float2 u2 = __half22float2(xin[c2 * 32 + lane]);
        float2 u3 = __half22float2(xin[c3 * 32 + lane]);
        s0 = add2(s0, add2(u0, u1));
        s1 = add2(s1, add2(u2, u3));
    }
    for (; e < end; e++) {
        int c = g_col[e];
        s0 = add2(s0, __half22float2(xin[c * 32 + lane]));
    }
    float invd = __fdividef(1.0f, (float)(end - beg));
    float2 s = add2(s0, s1);
    g_agg[(size_t)tower * (NN * 32) + r * 32 + lane] =
        __float22half2_rn(make_float2(s.x * invd, s.y * invd));
}

// ------------- dense kernel, 8 rows per warp ---------------------------------
#define RB 8

__device__ __forceinline__ void stage8(float2* __restrict__ stg2, int lane,
                                       const float2* v) {
    __syncwarp();
#pragma unroll
    for (int r = 0; r < RB; r++) stg2[r * 32 + lane] = v[r];
    __syncwarp();
}

__device__ __forceinline__ void mv8(const float4* __restrict__ Wm4,
                                    const float4* __restrict__ stg4,
                                    float2* __restrict__ out, int lane) {
    float2 acc0[RB], acc1[RB];
#pragma unroll
    for (int r = 0; r < RB; r++) {
        acc0[r] = make_float2(0.f, 0.f);
        acc1[r] = make_float2(0.f, 0.f);
    }
#pragma unroll
    for (int k4 = 0; k4 < 16; k4++) {
        float4 w0 = Wm4[(k4 << 6) + lane];        // W[2l][4k4..+3]
        float4 w1 = Wm4[(k4 << 6) + 32 + lane];   // W[2l+1][4k4..+3]
        float2 w0lo = make_float2(w0.x, w0.y), w0hi = make_float2(w0.z, w0.w);
        float2 w1lo = make_float2(w1.x, w1.y), w1hi = make_float2(w1.z, w1.w);
#pragma unroll
        for (int r = 0; r < RB; r++) {
            float4 s = stg4[r * 16 + k4];         // broadcast
            float2 slo = make_float2(s.x, s.y), shi = make_float2(s.z, s.w);
            acc0[r] = ffma2(slo, w0lo, acc0[r]);
            acc0[r] = ffma2(shi, w0hi, acc0[r]);
            acc1[r] = ffma2(slo, w1lo, acc1[r]);
            acc1[r] = ffma2(shi, w1hi, acc1[r]);
        }
    }
#pragma unroll
    for (int r = 0; r < RB; r++)
        out[r] = make_float2(acc0[r].x + acc0[r].y, acc1[r].x + acc1[r].y);
}

__global__ void __launch_bounds__(256, 2)
k_dense(const float* __restrict__ Wv, const float* __restrict__ Bv,
        const float* __restrict__ Wt, const float* __restrict__ Bt) {
    extern __shared__ float4 sdyn[];   // 3072 weight float4 + 8*128 staging
    float4* Ws4 = sdyn;                // 48 KB
    int tower = blockIdx.y;
    const float* W = tower ? Wt : Wv;
    const float* B = tower ? Bt : Bv;
    int t = threadIdx.x;
    for (int idx = t; idx < 3072; idx += 256) {
        int m = idx >> 10, rem = idx & 1023;
        int k4 = rem >> 6, j = (rem >> 5) & 1, l = rem & 31;
        const float4* gW4 = (const float4*)(W + m * 4096);
        Ws4[idx] = gW4[(2 * l + j) * 16 + k4];
    }
    __syncthreads();

    int lane = t & 31, warp = t >> 5;
    float4* stg4 = sdyn + 3072 + warp * 128;
    float2* stg2 = (float2*)stg4;

    __half2* xbuf = g_x + (size_t)tower * (NN * 32);
    const __half2* __restrict__ aggin = g_agg + (size_t)tower * (NN * 32);

    float2 b0 = ((const float2*)B)[lane];
    float2 b1 = ((const float2*)(B + 64))[lane];
    float2 b2 = ((const float2*)(B + 128))[lane];
    const float4* W0 = Ws4;
    const float4* W1 = Ws4 + 1024;
    const float4* W2 = Ws4 + 2048;

    int gw = blockIdx.x * 8 + warp;
    int stride = gridDim.x * 8 * RB;
    for (int r = gw * RB; r < NN; r += stride) {
        float2 x[RB], tmp[RB], xh[RB];
#pragma unroll
        for (int q = 0; q < RB; q++) x[q] = __half22float2(xbuf[(r + q) * 32 + lane]);
        // xhat = leaky(x@W1^T + b1) + id
        stage8(stg2, lane, x);
        mv8(W1, stg4, tmp, lane);
#pragma unroll
        for (int q = 0; q < RB; q++) {
            float2 idv = __half22float2(g_idh[(r + q) * 32 + lane]);
            xh[q] = make_float2(leaky(tmp[q].x + b1.x) + idv.x,
                                leaky(tmp[q].y + b1.y) + idv.y);
        }
        // h = leaky(agg@W0^T + b0)
        float2 a[RB];
#pragma unroll
        for (int q = 0; q < RB; q++) a[q] = __half22float2(aggin[(r + q) * 32 + lane]);
        stage8(stg2, lane, a);
        mv8(W0, stg4, tmp, lane);
        float2 h[RB];
#pragma unroll
        for (int q = 0; q < RB; q++)
            h[q] = make_float2(leaky(tmp[q].x + b0.x), leaky(tmp[q].y + b0.y));
        // out = leaky(h@W2^T + b2 + xhat), in-place on g_x (row-local)
        stage8(stg2, lane, h);
        mv8(W2, stg4, tmp, lane);
#pragma unroll
        for (int q = 0; q < RB; q++)
            xbuf[(r + q) * 32 + lane] = __float22half2_rn(
                make_float2(leaky(tmp[q].x + b2.x + xh[q].x),
                            leaky(tmp[q].y + b2.y + xh[q].y)));
    }
}

// ------------- final combine -------------------------------------------------
__global__ void k_combine(float2* __restrict__ out) {
    int i = blockIdx.x * blockDim.x + threadIdx.x;
    if (i < NN * 32) {
        float2 a = __half22float2(g_x[i]);
        float2 b = __half22float2(g_x[NN * 32 + i]);
        out[i] = make_float2(0.5f * (a.x + b.x), 0.5f * (a.y + b.y));
    }
}

// ------------- launch --------------------------------------------------------
extern "C" void kernel_launch(void* const* d_in, const int* in_sizes, int n_in,
                              void* d_out, int out_size) {
    const float* v_feat = (const float*)d_in[0];
    const float* t_feat = (const float*)d_in[1];
    const float* id_emb = (const float*)d_in[2];
    const float* v_pref = (const float*)d_in[3];
    const float* t_pref = (const float*)d_in[4];
    const float* v_W    = (const float*)d_in[5];
    const float* v_b    = (const float*)d_in[6];
    const float* t_W    = (const float*)d_in[7];
    const float* t_b    = (const float*)d_in[8];
    const int*   edges  = (const int*)d_in[9];
    const int* row = edges;
    const int* col = edges + NE;
    float2* out = (float2*)d_out;

    void *degp, *statep;
    cudaGetSymbolAddress(&degp, g_deg);
    cudaGetSymbolAddress(&statep, g_state);

    const int DENSE_SMEM = (3072 + 8 * 128) * sizeof(float4);  // 64 KB
    static int attr_done = 0;
    if (!attr_done) {
        cudaFuncSetAttribute(k_dense, cudaFuncAttributeMaxDynamicSharedMemorySize, DENSE_SMEM);
        attr_done = 1;
    }

    cudaMemsetAsync(degp, 0, NN * sizeof(int));
    cudaMemsetAsync(statep, 0, NB_SCAN * sizeof(unsigned long long));

    k_init_hist<<<20000, 256>>>(v_pref, v_feat, t_pref, t_feat, id_emb, row);
    k_scan<<<NB_SCAN, 1024>>>();
    k_fill<<<(NE + 255) / 256, 256>>>(row, col);

    dim3 dgrid(148, 2);
    for (int layer = 0; layer < 2; layer++) {
        k_agg<<<10000, 512>>>();
        k_dense<<<dgrid, 256, DENSE_SMEM>>>(v_W + layer * 3 * 4096, v_b + layer * 3 * 64,
                                            t_W + layer * 3 * 4096, t_b + layer * 3 * 64);
    }

    k_combine<<<10000, 256>>>(out);
}

// round 7
// speedup vs baseline: 2.5208x; 1.0451x over previous
#include <cuda_runtime.h>
#include <cuda_fp16.h>

#define NU 50000
#define NN 80000
#define NE 1600000
#define NB_SCAN 79   // ceil(80000/1024)

// ---------------- scratch (device globals; no allocation allowed) ----------
__device__ int    g_deg[NN];
__device__ int    g_off[NN + 1];
__device__ int    g_cur[NN + 1];
__device__ unsigned long long g_state[NB_SCAN];
__device__ int    g_col[NE];
__device__ __half2 g_x[2 * NN * 32];     // [tower][node][32 half2]
__device__ __half2 g_agg[2 * NN * 32];
__device__ __half2 g_idh[NN * 32];

__device__ __forceinline__ float leaky(float x) {
    return fmaxf(x, 0.01f * x);
}

// packed f32x2 fma / add (FFMA2 only reachable via PTX on sm_103a)
__device__ __forceinline__ float2 ffma2(float2 s, float2 w, float2 c) {
    unsigned long long rs = *reinterpret_cast<unsigned long long*>(&s);
    unsigned long long rw = *reinterpret_cast<unsigned long long*>(&w);
    unsigned long long rc = *reinterpret_cast<unsigned long long*>(&c);
    unsigned long long rd;
    asm("fma.rn.f32x2 %0, %1, %2, %3;" : "=l"(rd) : "l"(rs), "l"(rw), "l"(rc));
    return *reinterpret_cast<float2*>(&rd);
}
__device__ __forceinline__ float2 add2(float2 a, float2 b) {
    unsigned long long ra = *reinterpret_cast<unsigned long long*>(&a);
    unsigned long long rb = *reinterpret_cast<unsigned long long*>(&b);
    unsigned long long rd;
    asm("add.rn.f32x2 %0, %1, %2;" : "=l"(rd) : "l"(ra), "l"(rb));
    return *reinterpret_cast<float2*>(&rd);
}

// ------------- launch 1: normalize + id->half + edge histogram --------------
__global__ void k_init_hist(const float* __restrict__ v_pref, const float* __restrict__ v_feat,
                            const float* __restrict__ t_pref, const float* __restrict__ t_feat,
                            const float* __restrict__ id_emb,
                            const int* __restrict__ row) {
    int gid = blockIdx.x * blockDim.x + threadIdx.x;
    if (gid < NE) atomicAdd(&g_deg[row[gid]], 1);
    int w = gid >> 5;
    int lane = gid & 31;
    if (w < NN) {
        float2 iv = ((const float2*)id_emb)[w * 32 + lane];
        g_idh[w * 32 + lane] = __float22half2_rn(iv);
    }
    if (w >= 2 * NN) return;
    int tower = (w >= NN) ? 1 : 0;
    int n = w - tower * NN;
    const float2* src;
    if (tower == 0)
        src = (n < NU) ? (const float2*)v_pref + n * 32 : (const float2*)v_feat + (n - NU) * 32;
    else
        src = (n < NU) ? (const float2*)t_pref + n * 32 : (const float2*)t_feat + (n - NU) * 32;
    float2 v = src[lane];
    float ss = v.x * v.x + v.y * v.y;
#pragma unroll
    for (int o = 16; o > 0; o >>= 1) ss += __shfl_xor_sync(0xffffffffu, ss, o);
    float inv = 1.0f / fmaxf(sqrtf(ss), 1e-12f);
    g_x[w * 32 + lane] = __float22half2_rn(make_float2(v.x * inv, v.y * inv));
}

// ------------- launch 2: single-kernel scan (parallel lookback) -------------
__global__ void k_scan() {
    __shared__ int s[1024];
    __shared__ int s_prev;
    int tid = threadIdx.x;
    int i = blockIdx.x * 1024 + tid;
    int v = (i < NN) ? g_deg[i] : 0;
    s[tid] = v;
    __syncthreads();
#pragma unroll
    for (int off = 1; off < 1024; off <<= 1) {
        int t = (tid >= off) ? s[tid - off] : 0;
        __syncthreads();
        s[tid] += t;
        __syncthreads();
    }
    if (tid == 0) {
        unsigned long long mine = (1ULL << 32) | (unsigned)s[1023];
        atomicExch(&g_state[blockIdx.x], mine);
    }
    if (tid < 32) {
        int sum = 0;
        for (int j = tid; j < blockIdx.x; j += 32) {
            unsigned long long st;
            do { st = atomicAdd(&g_state[j], 0ULL); } while (!(st >> 32));
            sum += (int)(unsigned)st;
        }
#pragma unroll
        for (int o = 16; o > 0; o >>= 1) sum += __shfl_xor_sync(0xffffffffu, sum, o);
        if (tid == 0) s_prev = sum;
    }
    __syncthreads();
    int val = s[tid] + s_prev;
    if (i < NN) { g_off[i + 1] = val; g_cur[i + 1] = val; }
    if (i == 0) { g_off[0] = 0; g_cur[0] = 0; }
}

// ------------- launch 3: CSR fill -------------------------------------------
__global__ void k_fill(const int* __restrict__ row, const int* __restrict__ col) {
    int e = blockIdx.x * blockDim.x + threadIdx.x;
    if (e < NE) {
        int r = row[e];
        int p = atomicAdd(&g_cur[r], 1);
        g_col[p] = col[e];
    }
}

// ------------- aggregation: warp per row-tower, vector col loads -------------
__device__ __forceinline__ float2 pair4(const char* xb, int4 c) {
    // 4 gathered half2 loads -> one-level fp16 pairing -> fp32
    __half2 u0 = *(const __half2*)(xb + ((unsigned)c.x << 7));
    __half2 u1 = *(const __half2*)(xb + ((unsigned)c.y << 7));
    __half2 u2 = *(const __half2*)(xb + ((unsigned)c.z << 7));
    __half2 u3 = *(const __half2*)(xb + ((unsigned)c.w << 7));
    __half2 h01 = __hadd2(u0, u1);
    __half2 h23 = __hadd2(u2, u3);
    return add2(__half22float2(h01), __half22float2(h23));
}

__global__ void __launch_bounds__(512)
k_agg() {
    int gw = (blockIdx.x * 512 + threadIdx.x) >> 5;
    if (gw >= 2 * NN) return;
    int lane = threadIdx.x & 31;
    int tower = (gw >= NN) ? 1 : 0;
    int r = gw - tower * NN;
    const char* xb = (const char*)(g_x + (size_t)tower * (NN * 32)) + lane * 4;
    int beg = g_off[r], end = g_off[r + 1];
    float2 acc = {0.f, 0.f};
    int e = beg;
    // head: align e to 4-int boundary for int4 col loads
    int ealn = (beg + 3) & ~3;
    if (ealn > end) ealn = end;
    for (; e < ealn; e++) {
        int c = g_col[e];
        __half2 u = *(const __half2*)(xb + ((unsigned)c << 7));
        acc = add2(acc, __half22float2(u));
    }
    // main: 8 edges per iter (two int4 col loads, MLP=8)
    int end8 = e + ((end - e) & ~7);
    for (; e < end8; e += 8) {
        int4 ca = *(const int4*)(g_col + e);
        int4 cb = *(const int4*)(g_col + e + 4);
        float2 fa = pair4(xb, ca);
        float2 fb = pair4(xb, cb);
        acc = add2(acc, add2(fa, fb));
    }
    // mid: 4 edges
    if (end - e >= 4) {
        int4 ca = *(const int4*)(g_col + e);
        acc = add2(acc, pair4(xb, ca));
        e += 4;
    }
    // tail
    for (; e < end; e++) {
        int c = g_col[e];
        __half2 u = *(const __half2*)(xb + ((unsigned)c << 7));
        acc = add2(acc, __half22float2(u));
    }
    float invd = __fdividef(1.0f, (float)(end - beg));
    g_agg[(size_t)tower * (NN * 32) + r * 32 + lane] =
        __float22half2_rn(make_float2(acc.x * invd, acc.y * invd));
}

// ------------- dense kernel, 8 rows per warp ---------------------------------
#define RB 8

__device__ __forceinline__ void stage8(float2* __restrict__ stg2, int lane,
                                       const float2* v) {
    __syncwarp();
#pragma unroll
    for (int r = 0; r < RB; r++) stg2[r * 32 + lane] = v[r];
    __syncwarp();
}

__device__ __forceinline__ void mv8(const float4* __restrict__ Wm4,
                                    const float4* __restrict__ stg4,
                                    float2* __restrict__ out, int lane) {
    float2 acc0[RB], acc1[RB];
#pragma unroll
    for (int r = 0; r < RB; r++) {
        acc0[r] = make_float2(0.f, 0.f);
        acc1[r] = make_float2(0.f, 0.f);
    }
#pragma unroll
    for (int k4 = 0; k4 < 16; k4++) {
        float4 w0 = Wm4[(k4 << 6) + lane];        // W[2l][4k4..+3]
        float4 w1 = Wm4[(k4 << 6) + 32 + lane];   // W[2l+1][4k4..+3]
        float2 w0lo = make_float2(w0.x, w0.y), w0hi = make_float2(w0.z, w0.w);
        float2 w1lo = make_float2(w1.x, w1.y), w1hi = make_float2(w1.z, w1.w);
#pragma unroll
        for (int r = 0; r < RB; r++) {
            float4 s = stg4[r * 16 + k4];         // broadcast
            float2 slo = make_float2(s.x, s.y), shi = make_float2(s.z, s.w);
            acc0[r] = ffma2(slo, w0lo, acc0[r]);
            acc0[r] = ffma2(shi, w0hi, acc0[r]);
            acc1[r] = ffma2(slo, w1lo, acc1[r]);
            acc1[r] = ffma2(shi, w1hi, acc1[r]);
        }
    }
#pragma unroll
    for (int r = 0; r < RB; r++)
        out[r] = make_float2(acc0[r].x + acc0[r].y, acc1[r].x + acc1[r].y);
}

__global__ void __launch_bounds__(256, 2)
k_dense(const float* __restrict__ Wv, const float* __restrict__ Bv,
        const float* __restrict__ Wt, const float* __restrict__ Bt) {
    extern __shared__ float4 sdyn[];   // 3072 weight float4 + 8*128 staging
    float4* Ws4 = sdyn;                // 48 KB
    int tower = blockIdx.y;
    const float* W = tower ? Wt : Wv;
    const float* B = tower ? Bt : Bv;
    int t = threadIdx.x;
    for (int idx = t; idx < 3072; idx += 256) {
        int m = idx >> 10, rem = idx & 1023;
        int k4 = rem >> 6, j = (rem >> 5) & 1, l = rem & 31;
        const float4* gW4 = (const float4*)(W + m * 4096);
        Ws4[idx] = gW4[(2 * l + j) * 16 + k4];
    }
    __syncthreads();

    int lane = t & 31, warp = t >> 5;
    float4* stg4 = sdyn + 3072 + warp * 128;
    float2* stg2 = (float2*)stg4;

    __half2* xbuf = g_x + (size_t)tower * (NN * 32);
    const __half2* __restrict__ aggin = g_agg + (size_t)tower * (NN * 32);

    float2 b0 = ((const float2*)B)[lane];
    float2 b1 = ((const float2*)(B + 64))[lane];
    float2 b2 = ((const float2*)(B + 128))[lane];
    const float4* W0 = Ws4;
    const float4* W1 = Ws4 + 1024;
    const float4* W2 = Ws4 + 2048;

    int gw = blockIdx.x * 8 + warp;
    int stride = gridDim.x * 8 * RB;
    for (int r = gw * RB; r < NN; r += stride) {
        float2 x[RB], tmp[RB], xh[RB];
#pragma unroll
        for (int q = 0; q < RB; q++) x[q] = __half22float2(xbuf[(r + q) * 32 + lane]);
        // xhat = leaky(x@W1^T + b1) + id
        stage8(stg2, lane, x);
        mv8(W1, stg4, tmp, lane);
#pragma unroll
        for (int q = 0; q < RB; q++) {
            float2 idv = __half22float2(g_idh[(r + q) * 32 + lane]);
            xh[q] = make_float2(leaky(tmp[q].x + b1.x) + idv.x,
                                leaky(tmp[q].y + b1.y) + idv.y);
        }
        // h = leaky(agg@W0^T + b0)
        float2 a[RB];
#pragma unroll
        for (int q = 0; q < RB; q++) a[q] = __half22float2(aggin[(r + q) * 32 + lane]);
        stage8(stg2, lane, a);
        mv8(W0, stg4, tmp, lane);
        float2 h[RB];
#pragma unroll
        for (int q = 0; q < RB; q++)
            h[q] = make_float2(leaky(tmp[q].x + b0.x), leaky(tmp[q].y + b0.y));
        // out = leaky(h@W2^T + b2 + xhat), in-place on g_x (row-local)
        stage8(stg2, lane, h);
        mv8(W2, stg4, tmp, lane);
#pragma unroll
        for (int q = 0; q < RB; q++)
            xbuf[(r + q) * 32 + lane] = __float22half2_rn(
                make_float2(leaky(tmp[q].x + b2.x + xh[q].x),
                            leaky(tmp[q].y + b2.y + xh[q].y)));
    }
}

// ------------- final combine -------------------------------------------------
__global__ void k_combine(float2* __restrict__ out) {
    int i = blockIdx.x * blockDim.x + threadIdx.x;
    if (i < NN * 32) {
        float2 a = __half22float2(g_x[i]);
        float2 b = __half22float2(g_x[NN * 32 + i]);
        out[i] = make_float2(0.5f * (a.x + b.x), 0.5f * (a.y + b.y));
    }
}

// ------------- launch --------------------------------------------------------
extern "C" void kernel_launch(void* const* d_in, const int* in_sizes, int n_in,
                              void* d_out, int out_size) {
    const float* v_feat = (const float*)d_in[0];
    const float* t_feat = (const float*)d_in[1];
    const float* id_emb = (const float*)d_in[2];
    const float* v_pref = (const float*)d_in[3];
    const float* t_pref = (const float*)d_in[4];
    const float* v_W    = (const float*)d_in[5];
    const float* v_b    = (const float*)d_in[6];
    const float* t_W    = (const float*)d_in[7];
    const float* t_b    = (const float*)d_in[8];
    const int*   edges  = (const int*)d_in[9];
    const int* row = edges;
    const int* col = edges + NE;
    float2* out = (float2*)d_out;

    void *degp, *statep;
    cudaGetSymbolAddress(&degp, g_deg);
    cudaGetSymbolAddress(&statep, g_state);

    const int DENSE_SMEM = (3072 + 8 * 128) * sizeof(float4);  // 64 KB
    static int attr_done = 0;
    if (!attr_done) {
        cudaFuncSetAttribute(k_dense, cudaFuncAttributeMaxDynamicSharedMemorySize, DENSE_SMEM);
        attr_done = 1;
    }

    cudaMemsetAsync(degp, 0, NN * sizeof(int));
    cudaMemsetAsync(statep, 0, NB_SCAN * sizeof(unsigned long long));

    k_init_hist<<<20000, 256>>>(v_pref, v_feat, t_pref, t_feat, id_emb, row);
    k_scan<<<NB_SCAN, 1024>>>();
    k_fill<<<(NE + 255) / 256, 256>>>(row, col);

    dim3 dgrid(148, 2);
    for (int layer = 0; layer < 2; layer++) {
        k_agg<<<10000, 512>>>();
        k_dense<<<dgrid, 256, DENSE_SMEM>>>(v_W + layer * 3 * 4096, v_b + layer * 3 * 64,
                                            t_W + layer * 3 * 4096, t_b + layer * 3 * 64);
    }

    k_combine<<<10000, 256>>>(out);
}

// round 8
// speedup vs baseline: 2.6848x; 1.0651x over previous
#include <cuda_runtime.h>
#include <cuda_fp16.h>

#define NU 50000
#define NN 80000
#define NE 1600000
#define NB_SCAN 79   // ceil(80000/1024)

// ---------------- scratch (device globals; no allocation allowed) ----------
__device__ int    g_deg[NN];
__device__ int    g_off[NN + 1];
__device__ int    g_cur[NN + 1];
__device__ unsigned long long g_state[NB_SCAN];
__device__ int    g_col[NE];
__device__ __half2 g_x[2 * NN * 32];     // [tower][node][32 half2]
__device__ __half2 g_agg[2 * NN * 32];
__device__ __half2 g_idh[NN * 32];

__device__ __forceinline__ float leaky(float x) {
    return fmaxf(x, 0.01f * x);
}

// packed f32x2 fma / add (FFMA2 only reachable via PTX on sm_103a)
__device__ __forceinline__ float2 ffma2(float2 s, float2 w, float2 c) {
    unsigned long long rs = *reinterpret_cast<unsigned long long*>(&s);
    unsigned long long rw = *reinterpret_cast<unsigned long long*>(&w);
    unsigned long long rc = *reinterpret_cast<unsigned long long*>(&c);
    unsigned long long rd;
    asm("fma.rn.f32x2 %0, %1, %2, %3;" : "=l"(rd) : "l"(rs), "l"(rw), "l"(rc));
    return *reinterpret_cast<float2*>(&rd);
}
__device__ __forceinline__ float2 add2(float2 a, float2 b) {
    unsigned long long ra = *reinterpret_cast<unsigned long long*>(&a);
    unsigned long long rb = *reinterpret_cast<unsigned long long*>(&b);
    unsigned long long rd;
    asm("add.rn.f32x2 %0, %1, %2;" : "=l"(rd) : "l"(ra), "l"(rb));
    return *reinterpret_cast<float2*>(&rd);
}

// ------------- launch 1: normalize + id->half + edge histogram --------------
__global__ void k_init_hist(const float* __restrict__ v_pref, const float* __restrict__ v_feat,
                            const float* __restrict__ t_pref, const float* __restrict__ t_feat,
                            const float* __restrict__ id_emb,
                            const int* __restrict__ row) {
    int gid = blockIdx.x * blockDim.x + threadIdx.x;
    if (gid < NE) atomicAdd(&g_deg[row[gid]], 1);
    int w = gid >> 5;
    int lane = gid & 31;
    if (w < NN) {
        float2 iv = ((const float2*)id_emb)[w * 32 + lane];
        g_idh[w * 32 + lane] = __float22half2_rn(iv);
    }
    if (w >= 2 * NN) return;
    int tower = (w >= NN) ? 1 : 0;
    int n = w - tower * NN;
    const float2* src;
    if (tower == 0)
        src = (n < NU) ? (const float2*)v_pref + n * 32 : (const float2*)v_feat + (n - NU) * 32;
    else
        src = (n < NU) ? (const float2*)t_pref + n * 32 : (const float2*)t_feat + (n - NU) * 32;
    float2 v = src[lane];
    float ss = v.x * v.x + v.y * v.y;
#pragma unroll
    for (int o = 16; o > 0; o >>= 1) ss += __shfl_xor_sync(0xffffffffu, ss, o);
    float inv = 1.0f / fmaxf(sqrtf(ss), 1e-12f);
    g_x[w * 32 + lane] = __float22half2_rn(make_float2(v.x * inv, v.y * inv));
}

// ------------- launch 2: single-kernel scan (parallel lookback) -------------
__global__ void k_scan() {
    __shared__ int s[1024];
    __shared__ int s_prev;
    int tid = threadIdx.x;
    int i = blockIdx.x * 1024 + tid;
    int v = (i < NN) ? g_deg[i] : 0;
    s[tid] = v;
    __syncthreads();
#pragma unroll
    for (int off = 1; off < 1024; off <<= 1) {
        int t = (tid >= off) ? s[tid - off] : 0;
        __syncthreads();
        s[tid] += t;
        __syncthreads();
    }
    if (tid == 0) {
        unsigned long long mine = (1ULL << 32) | (unsigned)s[1023];
        atomicExch(&g_state[blockIdx.x], mine);
    }
    if (tid < 32) {
        int sum = 0;
        for (int j = tid; j < blockIdx.x; j += 32) {
            unsigned long long st;
            do { st = atomicAdd(&g_state[j], 0ULL); } while (!(st >> 32));
            sum += (int)(unsigned)st;
        }
#pragma unroll
        for (int o = 16; o > 0; o >>= 1) sum += __shfl_xor_sync(0xffffffffu, sum, o);
        if (tid == 0) s_prev = sum;
    }
    __syncthreads();
    int val = s[tid] + s_prev;
    if (i < NN) { g_off[i + 1] = val; g_cur[i + 1] = val; }
    if (i == 0) { g_off[0] = 0; g_cur[0] = 0; }
}

// ------------- launch 3: CSR fill -------------------------------------------
__global__ void k_fill(const int* __restrict__ row, const int* __restrict__ col) {
    int e = blockIdx.x * blockDim.x + threadIdx.x;
    if (e < NE) {
        int r = row[e];
        int p = atomicAdd(&g_cur[r], 1);
        g_col[p] = col[e];
    }
}

// ------------- aggregation: warp per row, BOTH towers per warp ---------------
// Per 4 edges: 4 offsets computed once, gathers issued for both tower bases.
__device__ __forceinline__ void pair4d(const char* xb0, const char* xb1, int4 c,
                                       float2& A, float2& B) {
    unsigned o0 = (unsigned)c.x << 7, o1 = (unsigned)c.y << 7;
    unsigned o2 = (unsigned)c.z << 7, o3 = (unsigned)c.w << 7;
    __half2 a0 = *(const __half2*)(xb0 + o0);
    __half2 a1 = *(const __half2*)(xb0 + o1);
    __half2 a2 = *(const __half2*)(xb0 + o2);
    __half2 a3 = *(const __half2*)(xb0 + o3);
    __half2 b0 = *(const __half2*)(xb1 + o0);
    __half2 b1 = *(const __half2*)(xb1 + o1);
    __half2 b2 = *(const __half2*)(xb1 + o2);
    __half2 b3 = *(const __half2*)(xb1 + o3);
    A = add2(A, add2(__half22float2(__hadd2(a0, a1)), __half22float2(__hadd2(a2, a3))));
    B = add2(B, add2(__half22float2(__hadd2(b0, b1)), __half22float2(__hadd2(b2, b3))));
}

__global__ void __launch_bounds__(512)
k_agg() {
    int r = (blockIdx.x * 512 + threadIdx.x) >> 5;
    if (r >= NN) return;
    int lane = threadIdx.x & 31;
    const char* xb0 = (const char*)g_x + lane * 4;
    const char* xb1 = (const char*)(g_x + (size_t)NN * 32) + lane * 4;
    int beg = g_off[r], end = g_off[r + 1];
    float2 accA = {0.f, 0.f}, accB = {0.f, 0.f};
    int e = beg;
    // head: align to int4 boundary
    int ealn = (beg + 3) & ~3;
    if (ealn > end) ealn = end;
    for (; e < ealn; e++) {
        unsigned off = (unsigned)g_col[e] << 7;
        accA = add2(accA, __half22float2(*(const __half2*)(xb0 + off)));
        accB = add2(accB, __half22float2(*(const __half2*)(xb1 + off)));
    }
    // main: 8 edges per iter
    int end8 = e + ((end - e) & ~7);
    for (; e < end8; e += 8) {
        int4 ca = *(const int4*)(g_col + e);
        int4 cb = *(const int4*)(g_col + e + 4);
        pair4d(xb0, xb1, ca, accA, accB);
        pair4d(xb0, xb1, cb, accA, accB);
    }
    // mid: 4 edges
    if (end - e >= 4) {
        int4 ca = *(const int4*)(g_col + e);
        pair4d(xb0, xb1, ca, accA, accB);
        e += 4;
    }
    // tail
    for (; e < end; e++) {
        unsigned off = (unsigned)g_col[e] << 7;
        accA = add2(accA, __half22float2(*(const __half2*)(xb0 + off)));
        accB = add2(accB, __half22float2(*(const __half2*)(xb1 + off)));
    }
    float invd = __fdividef(1.0f, (float)(end - beg));
    g_agg[r * 32 + lane] =
        __float22half2_rn(make_float2(accA.x * invd, accA.y * invd));
    g_agg[(size_t)NN * 32 + r * 32 + lane] =
        __float22half2_rn(make_float2(accB.x * invd, accB.y * invd));
}

// ------------- dense kernel, 8 rows per warp ---------------------------------
#define RB 8

__device__ __forceinline__ void stage8(float2* __restrict__ stg2, int lane,
                                       const float2* v) {
    __syncwarp();
#pragma unroll
    for (int r = 0; r < RB; r++) stg2[r * 32 + lane] = v[r];
    __syncwarp();
}

__device__ __forceinline__ void mv8(const float4* __restrict__ Wm4,
                                    const float4* __restrict__ stg4,
                                    float2* __restrict__ out, int lane) {
    float2 acc0[RB], acc1[RB];
#pragma unroll
    for (int r = 0; r < RB; r++) {
        acc0[r] = make_float2(0.f, 0.f);
        acc1[r] = make_float2(0.f, 0.f);
    }
#pragma unroll
    for (int k4 = 0; k4 < 16; k4++) {
        float4 w0 = Wm4[(k4 << 6) + lane];        // W[2l][4k4..+3]
        float4 w1 = Wm4[(k4 << 6) + 32 + lane];   // W[2l+1][4k4..+3]
        float2 w0lo = make_float2(w0.x, w0.y), w0hi = make_float2(w0.z, w0.w);
        float2 w1lo = make_float2(w1.x, w1.y), w1hi = make_float2(w1.z, w1.w);
#pragma unroll
        for (int r = 0; r < RB; r++) {
            float4 s = stg4[r * 16 + k4];         // broadcast
            float2 slo = make_float2(s.x, s.y), shi = make_float2(s.z, s.w);
            acc0[r] = ffma2(slo, w0lo, acc0[r]);
            acc0[r] = ffma2(shi, w0hi, acc0[r]);
            acc1[r] = ffma2(slo, w1lo, acc1[r]);
            acc1[r] = ffma2(shi, w1hi, acc1[r]);
        }
    }
#pragma unroll
    for (int r = 0; r < RB; r++)
        out[r] = make_float2(acc0[r].x + acc0[r].y, acc1[r].x + acc1[r].y);
}

__global__ void __launch_bounds__(256, 2)
k_dense(const float* __restrict__ Wv, const float* __restrict__ Bv,
        const float* __restrict__ Wt, const float* __restrict__ Bt) {
    extern __shared__ float4 sdyn[];   // 3072 weight float4 + 8*128 staging
    float4* Ws4 = sdyn;                // 48 KB
    int tower = blockIdx.y;
    const float* W = tower ? Wt : Wv;
    const float* B = tower ? Bt : Bv;
    int t = threadIdx.x;
    for (int idx = t; idx < 3072; idx += 256) {
        int m = idx >> 10, rem = idx & 1023;
        int k4 = rem >> 6, j = (rem >> 5) & 1, l = rem & 31;
        const float4* gW4 = (const float4*)(W + m * 4096);
        Ws4[idx] = gW4[(2 * l + j) * 16 + k4];
    }
    __syncthreads();

    int lane = t & 31, warp = t >> 5;
    float4* stg4 = sdyn + 3072 + warp * 128;
    float2* stg2 = (float2*)stg4;

    __half2* xbuf = g_x + (size_t)tower * (NN * 32);
    const __half2* __restrict__ aggin = g_agg + (size_t)tower * (NN * 32);

    float2 b0 = ((const float2*)B)[lane];
    float2 b1 = ((const float2*)(B + 64))[lane];
    float2 b2 = ((const float2*)(B + 128))[lane];
    const float4* W0 = Ws4;
    const float4* W1 = Ws4 + 1024;
    const float4* W2 = Ws4 + 2048;

    int gw = blockIdx.x * 8 + warp;
    int stride = gridDim.x * 8 * RB;
    for (int r = gw * RB; r < NN; r += stride) {
        float2 x[RB], tmp[RB], xh[RB];
#pragma unroll
        for (int q = 0; q < RB; q++) x[q] = __half22float2(xbuf[(r + q) * 32 + lane]);
        // xhat = leaky(x@W1^T + b1) + id
        stage8(stg2, lane, x);
        mv8(W1, stg4, tmp, lane);
#pragma unroll
        for (int q = 0; q < RB; q++) {
            float2 idv = __half22float2(g_idh[(r + q) * 32 + lane]);
            xh[q] = make_float2(leaky(tmp[q].x + b1.x) + idv.x,
                                leaky(tmp[q].y + b1.y) + idv.y);
        }
        // h = leaky(agg@W0^T + b0)
        float2 a[RB];
#pragma unroll
        for (int q = 0; q < RB; q++) a[q] = __half22float2(aggin[(r + q) * 32 + lane]);
        stage8(stg2, lane, a);
        mv8(W0, stg4, tmp, lane);
        float2 h[RB];
#pragma unroll
        for (int q = 0; q < RB; q++)
            h[q] = make_float2(leaky(tmp[q].x + b0.x), leaky(tmp[q].y + b0.y));
        // out = leaky(h@W2^T + b2 + xhat), in-place on g_x (row-local)
        stage8(stg2, lane, h);
        mv8(W2, stg4, tmp, lane);
#pragma unroll
        for (int q = 0; q < RB; q++)
            xbuf[(r + q) * 32 + lane] = __float22half2_rn(
                make_float2(leaky(tmp[q].x + b2.x + xh[q].x),
                            leaky(tmp[q].y + b2.y + xh[q].y)));
    }
}

// ------------- final combine -------------------------------------------------
__global__ void k_combine(float2* __restrict__ out) {
    int i = blockIdx.x * blockDim.x + threadIdx.x;
    if (i < NN * 32) {
        float2 a = __half22float2(g_x[i]);
        float2 b = __half22float2(g_x[NN * 32 + i]);
        out[i] = make_float2(0.5f * (a.x + b.x), 0.5f * (a.y + b.y));
    }
}

// ------------- launch --------------------------------------------------------
extern "C" void kernel_launch(void* const* d_in, const int* in_sizes, int n_in,
                              void* d_out, int out_size) {
    const float* v_feat = (const float*)d_in[0];
    const float* t_feat = (const float*)d_in[1];
    const float* id_emb = (const float*)d_in[2];
    const float* v_pref = (const float*)d_in[3];
    const float* t_pref = (const float*)d_in[4];
    const float* v_W    = (const float*)d_in[5];
    const float* v_b    = (const float*)d_in[6];
    const float* t_W    = (const float*)d_in[7];
    const float* t_b    = (const float*)d_in[8];
    const int*   edges  = (const int*)d_in[9];
    const int* row = edges;
    const int* col = edges + NE;
    float2* out = (float2*)d_out;

    void *degp, *statep;
    cudaGetSymbolAddress(&degp, g_deg);
    cudaGetSymbolAddress(&statep, g_state);

    const int DENSE_SMEM = (3072 + 8 * 128) * sizeof(float4);  // 64 KB
    static int attr_done = 0;
    if (!attr_done) {
        cudaFuncSetAttribute(k_dense, cudaFuncAttributeMaxDynamicSharedMemorySize, DENSE_SMEM);
        attr_done = 1;
    }

    cudaMemsetAsync(degp, 0, NN * sizeof(int));
    cudaMemsetAsync(statep, 0, NB_SCAN * sizeof(unsigned long long));

    k_init_hist<<<20000, 256>>>(v_pref, v_feat, t_pref, t_feat, id_emb, row);
    k_scan<<<NB_SCAN, 1024>>>();
    k_fill<<<(NE + 255) / 256, 256>>>(row, col);

    dim3 dgrid(148, 2);
    for (int layer = 0; layer < 2; layer++) {
        k_agg<<<5000, 512>>>();
        k_dense<<<dgrid, 256, DENSE_SMEM>>>(v_W + layer * 3 * 4096, v_b + layer * 3 * 64,
                                            t_W + layer * 3 * 4096, t_b + layer * 3 * 64);
    }

    k_combine<<<10000, 256>>>(out);
}

// round 10
// speedup vs baseline: 4.1334x; 1.5396x over previous
#include <cuda_runtime.h>
#include <cuda_fp16.h>
#include <cstdint>

#define NU 50000
#define NN 80000
#define NE 1600000
#define NB_SCAN 79   // ceil(80000/1024)

// ---------------- scratch (device globals; no allocation allowed) ----------
__device__ int    g_deg[NN];
__device__ int    g_off[NN + 1];
__device__ int    g_cur[NN + 1];
__device__ unsigned long long g_state[NB_SCAN];
__device__ int    g_col[NE];
__device__ __half2 g_x[2 * NN * 32];     // [tower][node][32 half2]
__device__ __half2 g_agg[2 * NN * 32];
__device__ __half2 g_idh[NN * 32];

__device__ __forceinline__ float leaky(float x) {
    return fmaxf(x, 0.01f * x);
}

__device__ __forceinline__ float2 add2(float2 a, float2 b) {
    unsigned long long ra = *reinterpret_cast<unsigned long long*>(&a);
    unsigned long long rb = *reinterpret_cast<unsigned long long*>(&b);
    unsigned long long rd;
    asm("add.rn.f32x2 %0, %1, %2;" : "=l"(rd) : "l"(ra), "l"(rb));
    return *reinterpret_cast<float2*>(&rd);
}

// ------------- launch 1: normalize + id->half + edge histogram --------------
__global__ void k_init_hist(const float* __restrict__ v_pref, const float* __restrict__ v_feat,
                            const float* __restrict__ t_pref, const float* __restrict__ t_feat,
                            const float* __restrict__ id_emb,
                            const int* __restrict__ row) {
    int gid = blockIdx.x * blockDim.x + threadIdx.x;
    if (gid < NE) atomicAdd(&g_deg[row[gid]], 1);
    int w = gid >> 5;
    int lane = gid & 31;
    if (w < NN) {
        float2 iv = ((const float2*)id_emb)[w * 32 + lane];
        g_idh[w * 32 + lane] = __float22half2_rn(iv);
    }
    if (w >= 2 * NN) return;
    int tower = (w >= NN) ? 1 : 0;
    int n = w - tower * NN;
    const float2* src;
    if (tower == 0)
        src = (n < NU) ? (const float2*)v_pref + n * 32 : (const float2*)v_feat + (n - NU) * 32;
    else
        src = (n < NU) ? (const float2*)t_pref + n * 32 : (const float2*)t_feat + (n - NU) * 32;
    float2 v = src[lane];
    float ss = v.x * v.x + v.y * v.y;
#pragma unroll
    for (int o = 16; o > 0; o >>= 1) ss += __shfl_xor_sync(0xffffffffu, ss, o);
    float inv = 1.0f / fmaxf(sqrtf(ss), 1e-12f);
    g_x[w * 32 + lane] = __float22half2_rn(make_float2(v.x * inv, v.y * inv));
}

// ------------- launch 2: single-kernel scan (parallel lookback) -------------
__global__ void k_scan() {
    __shared__ int s[1024];
    __shared__ int s_prev;
    int tid = threadIdx.x;
    int i = blockIdx.x * 1024 + tid;
    int v = (i < NN) ? g_deg[i] : 0;
    s[tid] = v;
    __syncthreads();
#pragma unroll
    for (int off = 1; off < 1024; off <<= 1) {
        int t = (tid >= off) ? s[tid - off] : 0;
        __syncthreads();
        s[tid] += t;
        __syncthreads();
    }
    if (tid == 0) {
        unsigned long long mine = (1ULL << 32) | (unsigned)s[1023];
        atomicExch(&g_state[blockIdx.x], mine);
    }
    if (tid < 32) {
        int sum = 0;
        for (int j = tid; j < blockIdx.x; j += 32) {
            unsigned long long st;
            do { st = atomicAdd(&g_state[j], 0ULL); } while (!(st >> 32));
            sum += (int)(unsigned)st;
        }
#pragma unroll
        for (int o = 16; o > 0; o >>= 1) sum += __shfl_xor_sync(0xffffffffu, sum, o);
        if (tid == 0) s_prev = sum;
    }
    __syncthreads();
    int val = s[tid] + s_prev;
    if (i < NN) { g_off[i + 1] = val; g_cur[i + 1] = val; }
    if (i == 0) { g_off[0] = 0; g_cur[0] = 0; }
}

// ------------- launch 3: CSR fill -------------------------------------------
__global__ void k_fill(const int* __restrict__ row, const int* __restrict__ col) {
    int e = blockIdx.x * blockDim.x + threadIdx.x;
    if (e < NE) {
        int r = row[e];
        int p = atomicAdd(&g_cur[r], 1);
        g_col[p] = col[e];
    }
}

// ------------- aggregation: warp per row, BOTH towers per warp ---------------
__device__ __forceinline__ void pair4d(const char* xb0, const char* xb1, int4 c,
                                       float2& A, float2& B) {
    unsigned o0 = (unsigned)c.x << 7, o1 = (unsigned)c.y << 7;
    unsigned o2 = (unsigned)c.z << 7, o3 = (unsigned)c.w << 7;
    __half2 a0 = *(const __half2*)(xb0 + o0);
    __half2 a1 = *(const __half2*)(xb0 + o1);
    __half2 a2 = *(const __half2*)(xb0 + o2);
    __half2 a3 = *(const __half2*)(xb0 + o3);
    __half2 b0 = *(const __half2*)(xb1 + o0);
    __half2 b1 = *(const __half2*)(xb1 + o1);
    __half2 b2 = *(const __half2*)(xb1 + o2);
    __half2 b3 = *(const __half2*)(xb1 + o3);
    A = add2(A, add2(__half22float2(__hadd2(a0, a1)), __half22float2(__hadd2(a2, a3))));
    B = add2(B, add2(__half22float2(__hadd2(b0, b1)), __half22float2(__hadd2(b2, b3))));
}

__global__ void __launch_bounds__(512)
k_agg() {
    int r = (blockIdx.x * 512 + threadIdx.x) >> 5;
    if (r >= NN) return;
    int lane = threadIdx.x & 31;
    const char* xb0 = (const char*)g_x + lane * 4;
    const char* xb1 = (const char*)(g_x + (size_t)NN * 32) + lane * 4;
    int beg = g_off[r], end = g_off[r + 1];
    float2 accA = {0.f, 0.f}, accB = {0.f, 0.f};
    int e = beg;
    int ealn = (beg + 3) & ~3;
    if (ealn > end) ealn = end;
    for (; e < ealn; e++) {
        unsigned off = (unsigned)g_col[e] << 7;
        accA = add2(accA, __half22float2(*(const __half2*)(xb0 + off)));
        accB = add2(accB, __half22float2(*(const __half2*)(xb1 + off)));
    }
    int end8 = e + ((end - e) & ~7);
    for (; e < end8; e += 8) {
        int4 ca = *(const int4*)(g_col + e);
        int4 cb = *(const int4*)(g_col + e + 4);
        pair4d(xb0, xb1, ca, accA, accB);
        pair4d(xb0, xb1, cb, accA, accB);
    }
    if (end - e >= 4) {
        int4 ca = *(const int4*)(g_col + e);
        pair4d(xb0, xb1, ca, accA, accB);
        e += 4;
    }
    for (; e < end; e++) {
        unsigned off = (unsigned)g_col[e] << 7;
        accA = add2(accA, __half22float2(*(const __half2*)(xb0 + off)));
        accB = add2(accB, __half22float2(*(const __half2*)(xb1 + off)));
    }
    float invd = __fdividef(1.0f, (float)(end - beg));
    g_agg[r * 32 + lane] =
        __float22half2_rn(make_float2(accA.x * invd, accA.y * invd));
    g_agg[(size_t)NN * 32 + r * 32 + lane] =
        __float22half2_rn(make_float2(accB.x * invd, accB.y * invd));
}

// ------------- dense via tensor cores (mma.sync m16n8k16 f16->f32) ----------
// smem: Wh[3][64k][64n] fp16, rows of 128B, 16B-chunk XOR swizzle (chunk ^= k&7)
// staging per warp: bufX (x, then h) + bufA (agg), 16 rows x 128B each, same swizzle.

__device__ __forceinline__ void ldmA(uint32_t addr, uint32_t& a0, uint32_t& a1,
                                     uint32_t& a2, uint32_t& a3) {
    asm volatile("ldmatrix.sync.aligned.m8n8.x4.shared.b16 {%0,%1,%2,%3}, [%4];"
                 : "=r"(a0), "=r"(a1), "=r"(a2), "=r"(a3) : "r"(addr));
}
__device__ __forceinline__ void ldmB(uint32_t addr, uint32_t& b0, uint32_t& b1) {
    asm volatile("ldmatrix.sync.aligned.m8n8.x2.trans.shared.b16 {%0,%1}, [%2];"
                 : "=r"(b0), "=r"(b1) : "r"(addr));
}
__device__ __forceinline__ void hmma(float& c0, float& c1, float& c2, float& c3,
                                     uint32_t a0, uint32_t a1, uint32_t a2, uint32_t a3,
                                     uint32_t b0, uint32_t b1) {
    asm volatile("mma.sync.aligned.m16n8k16.row.col.f32.f16.f16.f32 "
                 "{%0,%1,%2,%3}, {%4,%5,%6,%7}, {%8,%9}, {%0,%1,%2,%3};"
                 : "+f"(c0), "+f"(c1), "+f"(c2), "+f"(c3)
                 : "r"(a0), "r"(a1), "r"(a2), "r"(a3), "r"(b0), "r"(b1));
}

// C[8 tiles][4] += A(16x64 staged) @ Wm^T  (Wm smem = W[k][n] fp16 swizzled)
__device__ __forceinline__ void mv_mma(uint32_t uA, uint32_t uWm, float* c, int lane) {
    int r = lane & 15;
    int hiA = lane >> 4;
    int rsw = r & 7;
#pragma unroll
    for (int s = 0; s < 4; s++) {
        uint32_t a0, a1, a2, a3;
        ldmA(uA + r * 128 + (((2 * s + hiA) ^ rsw) << 4), a0, a1, a2, a3);
        uint32_t rowB = uWm + (16 * s + r) * 128;
#pragma unroll
        for (int j = 0; j < 8; j++) {
            uint32_t b0, b1;
            ldmB(rowB + ((j ^ rsw) << 4), b0, b1);
            hmma(c[j * 4], c[j * 4 + 1], c[j * 4 + 2], c[j * 4 + 3],
                 a0, a1, a2, a3, b0, b1);
        }
    }
}

#define DENSE_SMEM_BYTES (24576 + 8 * 4096)   // 3 W matrices + 8 warps * (bufX+bufA)

__global__ void __launch_bounds__(256, 2)
k_dense(const float* __restrict__ Wv, const float* __restrict__ Bv,
        const float* __restrict__ Wt, const float* __restrict__ Bt) {
    extern __shared__ char sm[];
    int tower = blockIdx.y;
    const float* W = tower ? Wt : Wv;
    const float* Bb = tower ? Bt : Bv;
    int t = threadIdx.x;

    // load weights -> fp16 smem, Wh[m][k][n] swizzled
    __half* Wsm = (__half*)sm;
    for (int idx = t; idx < 3 * 4096; idx += 256) {
        int m = idx >> 12;
        int n = (idx >> 6) & 63;   // output row of W
        int k = idx & 63;          // input col (coalesced gmem read)
        int chunk = (n >> 3) ^ (k & 7);
        Wsm[m * 4096 + k * 64 + chunk * 8 + (n & 7)] = __float2half_rn(W[idx]);
    }
    __syncthreads();

    int lane = t & 31, warp = t >> 5;
    char* bufX = sm + 24576 + warp * 4096;
    char* bufA = bufX + 2048;
    uint32_t uW = (uint32_t)__cvta_generic_to_shared(Wsm);
    uint32_t uX = (uint32_t)__cvta_generic_to_shared(bufX);
    uint32_t uA = (uint32_t)__cvta_generic_to_shared(bufA);

    const char* xg = (const char*)(g_x + (size_t)tower * (NN * 32));
    const char* ag = (const char*)(g_agg + (size_t)tower * (NN * 32));
    __half2* xout = g_x + (size_t)tower * (NN * 32);

    const float* b0p = Bb;
    const float* b1p = Bb + 64;
    const float* b2p = Bb + 128;
    int cp = lane & 3;
    int rl = lane >> 2;          // local row 0..7 in C fragments
    int rlsw = rl & 7;

    // 5000 groups of 16 rows; gridDim.x*8 warps per tower
    for (int g = blockIdx.x * 8 + warp; g < NN / 16; g += gridDim.x * 8) {
        int rbase = g * 16;
        // stage x and agg (swizzled)
#pragma unroll
        for (int i = 0; i < 4; i++) {
            int idx = i * 32 + lane;
            int r = idx >> 3, c = idx & 7;
            uint4 vx = *(const uint4*)(xg + (size_t)(rbase + r) * 128 + c * 16);
            uint4 va = *(const uint4*)(ag + (size_t)(rbase + r) * 128 + c * 16);
            int csw = c ^ (r & 7);
            *(uint4*)(bufX + r * 128 + csw * 16) = vx;
            *(uint4*)(bufA + r * 128 + csw * 16) = va;
        }
        __syncwarp();

        // ---- mv1: xh = leaky(x@W1^T + b1) + id  (kept in fp32 fragments)
        float xh[32];
#pragma unroll
        for (int i = 0; i < 32; i++) xh[i] = 0.f;
        mv_mma(uX, uW + 8192, xh, lane);
        int row0 = rbase + rl;
#pragma unroll
        for (int j = 0; j < 8; j++) {
            float2 bb = ((const float2*)b1p)[j * 4 + cp];
            float2 i0 = __half22float2(g_idh[row0 * 32 + j * 4 + cp]);
            float2 i1 = __half22float2(g_idh[(row0 + 8) * 32 + j * 4 + cp]);
            xh[j * 4 + 0] = leaky(xh[j * 4 + 0] + bb.x) + i0.x;
            xh[j * 4 + 1] = leaky(xh[j * 4 + 1] + bb.y) + i0.y;
            xh[j * 4 + 2] = leaky(xh[j * 4 + 2] + bb.x) + i1.x;
            xh[j * 4 + 3] = leaky(xh[j * 4 + 3] + bb.y) + i1.y;
        }

        // ---- mv0: h = leaky(agg@W0^T + b0) -> fp16 restage into bufX
        float c2[32];
#pragma unroll
        for (int i = 0; i < 32; i++) c2[i] = 0.f;
        mv_mma(uA, uW, c2, lane);
        __syncwarp();   // all ldmatrix reads of bufX (mv1) done before overwrite
#pragma unroll
        for (int j = 0; j < 8; j++) {
            float2 bb = ((const float2*)b0p)[j * 4 + cp];
            __half2 h0 = __floats2half2_rn(leaky(c2[j * 4 + 0] + bb.x),
                                           leaky(c2[j * 4 + 1] + bb.y));
            __half2 h1 = __floats2half2_rn(leaky(c2[j * 4 + 2] + bb.x),
                                           leaky(c2[j * 4 + 3] + bb.y));
            int ch = (j ^ rlsw) << 4;
            *(__half2*)(bufX + rl * 128 + ch + cp * 4) = h0;
            *(__half2*)(bufX + (rl + 8) * 128 + ch + cp * 4) = h1;
        }
        __syncwarp();

        // ---- mv2: out = leaky(h@W2^T + b2 + xh); accumulate onto xh+b2
#pragma unroll
        for (int j = 0; j < 8; j++) {
            float2 bb = ((const float2*)b2p)[j * 4 + cp];
            xh[j * 4 + 0] += bb.x;
            xh[j * 4 + 1] += bb.y;
            xh[j * 4 + 2] += bb.x;
            xh[j * 4 + 3] += bb.y;
        }
        mv_mma(uX, uW + 16384, xh, lane);
#pragma unroll
        for (int j = 0; j < 8; j++) {
            __half2 o0 = __floats2half2_rn(leaky(xh[j * 4 + 0]), leaky(xh[j * 4 + 1]));
            __half2 o1 = __floats2half2_rn(leaky(xh[j * 4 + 2]), leaky(xh[j * 4 + 3]));
            xout[row0 * 32 + j * 4 + cp] = o0;
            xout[(row0 + 8) * 32 + j * 4 + cp] = o1;
        }
    }
}

// ------------- final combine -------------------------------------------------
__global__ void k_combine(float2* __restrict__ out) {
    int i = blockIdx.x * blockDim.x + threadIdx.x;
    if (i < NN * 32) {
        float2 a = __half22float2(g_x[i]);
        float2 b = __half22float2(g_x[NN * 32 + i]);
        out[i] = make_float2(0.5f * (a.x + b.x), 0.5f * (a.y + b.y));
    }
}

// ------------- launch --------------------------------------------------------
extern "C" void kernel_launch(void* const* d_in, const int* in_sizes, int n_in,
                              void* d_out, int out_size) {
    const float* v_feat = (const float*)d_in[0];
    const float* t_feat = (const float*)d_in[1];
    const float* id_emb = (const float*)d_in[2];
    const float* v_pref = (const float*)d_in[3];
    const float* t_pref = (const float*)d_in[4];
    const float* v_W    = (const float*)d_in[5];
    const float* v_b    = (const float*)d_in[6];
    const float* t_W    = (const float*)d_in[7];
    const float* t_b    = (const float*)d_in[8];
    const int*   edges  = (const int*)d_in[9];
    const int* row = edges;
    const int* col = edges + NE;
    float2* out = (float2*)d_out;

    void *degp, *statep;
    cudaGetSymbolAddress(&degp, g_deg);
    cudaGetSymbolAddress(&statep, g_state);

    static int attr_done = 0;
    if (!attr_done) {
        cudaFuncSetAttribute(k_dense, cudaFuncAttributeMaxDynamicSharedMemorySize,
                             DENSE_SMEM_BYTES);
        attr_done = 1;
    }

    cudaMemsetAsync(degp, 0, NN * sizeof(int));
    cudaMemsetAsync(statep, 0, NB_SCAN * sizeof(unsigned long long));

    k_init_hist<<<20000, 256>>>(v_pref, v_feat, t_pref, t_feat, id_emb, row);
    k_scan<<<NB_SCAN, 1024>>>();
    k_fill<<<(NE + 255) / 256, 256>>>(row, col);

    dim3 dgrid(125, 2);   // 125*8 warps = 1000 -> 5 groups of 16 rows each, exact
    for (int layer = 0; layer < 2; layer++) {
        k_agg<<<5000, 512>>>();
        k_dense<<<dgrid, 256, DENSE_SMEM_BYTES>>>(
            v_W + layer * 3 * 4096, v_b + layer * 3 * 64,
            t_W + layer * 3 * 4096, t_b + layer * 3 * 64);
    }

    k_combine<<<10000, 256>>>(out);
}

// round 11
// speedup vs baseline: 4.3316x; 1.0479x over previous
#include <cuda_runtime.h>
#include <cuda_fp16.h>
#include <cstdint>

#define NU 50000
#define NN 80000
#define NE 1600000
#define NB_SCAN 79   // ceil(80000/1024)
#define NCOL_PAD (NE + 7 * NN)

// ---------------- scratch (device globals; no allocation allowed) ----------
__device__ int    g_deg[NN];
__device__ int    g_off[NN + 1];      // PADDED offsets (multiples of 8)
__device__ int    g_cur[NN + 1];
__device__ unsigned long long g_state[NB_SCAN];
__device__ int    g_col[NCOL_PAD];
// interleaved feature storage: [node][towerA 32 half2][towerB 32 half2]
// row NN = dummy zero row (gather target for CSR padding)
__device__ __half2 g_x[(NN + 8) * 64];
__device__ __half2 g_agg[NN * 64];
__device__ __half2 g_idh[NN * 32];

__device__ __forceinline__ float leaky(float x) {
    return fmaxf(x, 0.01f * x);
}

__device__ __forceinline__ float2 add2(float2 a, float2 b) {
    unsigned long long ra = *reinterpret_cast<unsigned long long*>(&a);
    unsigned long long rb = *reinterpret_cast<unsigned long long*>(&b);
    unsigned long long rd;
    asm("add.rn.f32x2 %0, %1, %2;" : "=l"(rd) : "l"(ra), "l"(rb));
    return *reinterpret_cast<float2*>(&rd);
}

// ------------- launch 1: normalize + id->half + edge histogram --------------
__global__ void k_init_hist(const float* __restrict__ v_pref, const float* __restrict__ v_feat,
                            const float* __restrict__ t_pref, const float* __restrict__ t_feat,
                            const float* __restrict__ id_emb,
                            const int* __restrict__ row) {
    int gid = blockIdx.x * blockDim.x + threadIdx.x;
    if (gid < NE) atomicAdd(&g_deg[row[gid]], 1);
    if (gid < 64) g_x[NN * 64 + gid] = __float2half2_rn(0.f);   // dummy zero row
    int w = gid >> 5;
    int lane = gid & 31;
    if (w < NN) {
        float2 iv = ((const float2*)id_emb)[w * 32 + lane];
        g_idh[w * 32 + lane] = __float22half2_rn(iv);
    }
    if (w >= 2 * NN) return;
    int tower = (w >= NN) ? 1 : 0;
    int n = w - tower * NN;
    const float2* src;
    if (tower == 0)
        src = (n < NU) ? (const float2*)v_pref + n * 32 : (const float2*)v_feat + (n - NU) * 32;
    else
        src = (n < NU) ? (const float2*)t_pref + n * 32 : (const float2*)t_feat + (n - NU) * 32;
    float2 v = src[lane];
    float ss = v.x * v.x + v.y * v.y;
#pragma unroll
    for (int o = 16; o > 0; o >>= 1) ss += __shfl_xor_sync(0xffffffffu, ss, o);
    float inv = 1.0f / fmaxf(sqrtf(ss), 1e-12f);
    g_x[n * 64 + tower * 32 + lane] = __float22half2_rn(make_float2(v.x * inv, v.y * inv));
}

// ------------- launch 2: scan of PADDED degrees + pad-slot fill --------------
__global__ void k_scan() {
    __shared__ int s[1024];
    __shared__ int s_prev;
    int tid = threadIdx.x;
    int i = blockIdx.x * 1024 + tid;
    int dv = (i < NN) ? g_deg[i] : 0;
    int v = (dv + 7) & ~7;             // padded degree
    s[tid] = v;
    __syncthreads();
#pragma unroll
    for (int off = 1; off < 1024; off <<= 1) {
        int t = (tid >= off) ? s[tid - off] : 0;
        __syncthreads();
        s[tid] += t;
        __syncthreads();
    }
    if (tid == 0) {
        unsigned long long mine = (1ULL << 32) | (unsigned)s[1023];
        atomicExch(&g_state[blockIdx.x], mine);
    }
    if (tid < 32) {
        int sum = 0;
        for (int j = tid; j < blockIdx.x; j += 32) {
            unsigned long long st;
            do { st = atomicAdd(&g_state[j], 0ULL); } while (!(st >> 32));
            sum += (int)(unsigned)st;
        }
#pragma unroll
        for (int o = 16; o > 0; o >>= 1) sum += __shfl_xor_sync(0xffffffffu, sum, o);
        if (tid == 0) s_prev = sum;
    }
    __syncthreads();
    int val = s[tid] + s_prev;          // inclusive padded offset (= off[i+1])
    if (i < NN) {
        g_off[i + 1] = val;
        g_cur[i + 1] = val;
        // fill this row's pad slots with the dummy row index NN
        for (int p = val - (v - dv); p < val; p++) g_col[p] = NN;
    }
    if (i == 0) { g_off[0] = 0; g_cur[0] = 0; }
}

// ------------- launch 3: CSR fill -------------------------------------------
__global__ void k_fill(const int* __restrict__ row, const int* __restrict__ col) {
    int e = blockIdx.x * blockDim.x + threadIdx.x;
    if (e < NE) {
        int r = row[e];
        int p = atomicAdd(&g_cur[r], 1);
        g_col[p] = col[e];
    }
}

// ------------- aggregation: warp/row, both towers, branch-free 8-edge loop ---
__device__ __forceinline__ void quadAB(const char* xb, int4 c, float2& A, float2& B) {
    const char* p0 = xb + ((unsigned)c.x << 8);
    const char* p1 = xb + ((unsigned)c.y << 8);
    const char* p2 = xb + ((unsigned)c.z << 8);
    const char* p3 = xb + ((unsigned)c.w << 8);
    __half2 a0 = *(const __half2*)p0;
    __half2 a1 = *(const __half2*)p1;
    __half2 a2 = *(const __half2*)p2;
    __half2 a3 = *(const __half2*)p3;
    __half2 b0 = *(const __half2*)(p0 + 128);
    __half2 b1 = *(const __half2*)(p1 + 128);
    __half2 b2 = *(const __half2*)(p2 + 128);
    __half2 b3 = *(const __half2*)(p3 + 128);
    __half2 qA = __hadd2(__hadd2(a0, a1), __hadd2(a2, a3));
    __half2 qB = __hadd2(__hadd2(b0, b1), __hadd2(b2, b3));
    A = add2(A, __half22float2(qA));
    B = add2(B, __half22float2(qB));
}

__global__ void __launch_bounds__(512)
k_agg() {
    int r = (blockIdx.x * 512 + threadIdx.x) >> 5;
    if (r >= NN) return;
    int lane = threadIdx.x & 31;
    const char* xb = (const char*)g_x + lane * 4;
    int beg = g_off[r], end = g_off[r + 1];
    float2 A = {0.f, 0.f}, B = {0.f, 0.f};
    for (int e = beg; e < end; e += 8) {
        int4 ca = *(const int4*)(g_col + e);
        int4 cb = *(const int4*)(g_col + e + 4);
        quadAB(xb, ca, A, B);
        quadAB(xb, cb, A, B);
    }
    float invd = __fdividef(1.0f, (float)g_deg[r]);
    g_agg[r * 64 + lane]      = __float22half2_rn(make_float2(A.x * invd, A.y * invd));
    g_agg[r * 64 + 32 + lane] = __float22half2_rn(make_float2(B.x * invd, B.y * invd));
}

// ------------- dense via tensor cores (mma.sync m16n8k16 f16->f32) ----------
__device__ __forceinline__ void ldmA(uint32_t addr, uint32_t& a0, uint32_t& a1,
                                     uint32_t& a2, uint32_t& a3) {
    asm volatile("ldmatrix.sync.aligned.m8n8.x4.shared.b16 {%0,%1,%2,%3}, [%4];"
                 : "=r"(a0), "=r"(a1), "=r"(a2), "=r"(a3) : "r"(addr));
}
__device__ __forceinline__ void ldmB(uint32_t addr, uint32_t& b0, uint32_t& b1) {
    asm volatile("ldmatrix.sync.aligned.m8n8.x2.trans.shared.b16 {%0,%1}, [%2];"
                 : "=r"(b0), "=r"(b1) : "r"(addr));
}
__device__ __forceinline__ void hmma(float& c0, float& c1, float& c2, float& c3,
                                     uint32_t a0, uint32_t a1, uint32_t a2, uint32_t a3,
                                     uint32_t b0, uint32_t b1) {
    asm volatile("mma.sync.aligned.m16n8k16.row.col.f32.f16.f16.f32 "
                 "{%0,%1,%2,%3}, {%4,%5,%6,%7}, {%8,%9}, {%0,%1,%2,%3};"
                 : "+f"(c0), "+f"(c1), "+f"(c2), "+f"(c3)
                 : "r"(a0), "r"(a1), "r"(a2), "r"(a3), "r"(b0), "r"(b1));
}

__device__ __forceinline__ void mv_mma(uint32_t uA, uint32_t uWm, float* c, int lane) {
    int r = lane & 15;
    int hiA = lane >> 4;
    int rsw = r & 7;
#pragma unroll
    for (int s = 0; s < 4; s++) {
        uint32_t a0, a1, a2, a3;
        ldmA(uA + r * 128 + (((2 * s + hiA) ^ rsw) << 4), a0, a1, a2, a3);
        uint32_t rowB = uWm + (16 * s + r) * 128;
#pragma unroll
        for (int j = 0; j < 8; j++) {
            uint32_t b0, b1;
            ldmB(rowB + ((j ^ rsw) << 4), b0, b1);
            hmma(c[j * 4], c[j * 4 + 1], c[j * 4 + 2], c[j * 4 + 3],
                 a0, a1, a2, a3, b0, b1);
        }
    }
}

#define DENSE_SMEM_BYTES (24576 + 8 * 4096)

__global__ void __launch_bounds__(256, 2)
k_dense(const float* __restrict__ Wv, const float* __restrict__ Bv,
        const float* __restrict__ Wt, const float* __restrict__ Bt) {
    extern __shared__ char sm[];
    int tower = blockIdx.y;
    const float* W = tower ? Wt : Wv;
    const float* Bb = tower ? Bt : Bv;
    int t = threadIdx.x;

    __half* Wsm = (__half*)sm;
    for (int idx = t; idx < 3 * 4096; idx += 256) {
        int m = idx >> 12;
        int n = (idx >> 6) & 63;
        int k = idx & 63;
        int chunk = (n >> 3) ^ (k & 7);
        Wsm[m * 4096 + k * 64 + chunk * 8 + (n & 7)] = __float2half_rn(W[idx]);
    }
    __syncthreads();

    int lane = t & 31, warp = t >> 5;
    char* bufX = sm + 24576 + warp * 4096;
    char* bufA = bufX + 2048;
    uint32_t uW = (uint32_t)__cvta_generic_to_shared(Wsm);
    uint32_t uX = (uint32_t)__cvta_generic_to_shared(bufX);
    uint32_t uA = (uint32_t)__cvta_generic_to_shared(bufA);

    // interleaved layout: node row stride 256B, tower offset 128B
    const char* xg = (const char*)g_x + tower * 128;
    const char* ag = (const char*)g_agg + tower * 128;
    char* xo = (char*)g_x + tower * 128;

    const float* b0p = Bb;
    const float* b1p = Bb + 64;
    const float* b2p = Bb + 128;
    int cp = lane & 3;
    int rl = lane >> 2;
    int rlsw = rl & 7;

    for (int g = blockIdx.x * 8 + warp; g < NN / 16; g += gridDim.x * 8) {
        int rbase = g * 16;
#pragma unroll
        for (int i = 0; i < 4; i++) {
            int idx = i * 32 + lane;
            int r = idx >> 3, c = idx & 7;
            uint4 vx = *(const uint4*)(xg + (size_t)(rbase + r) * 256 + c * 16);
            uint4 va = *(const uint4*)(ag + (size_t)(rbase + r) * 256 + c * 16);
            int csw = c ^ (r & 7);
            *(uint4*)(bufX + r * 128 + csw * 16) = vx;
            *(uint4*)(bufA + r * 128 + csw * 16) = va;
        }
        __syncwarp();

        // ---- mv1: xh = leaky(x@W1^T + b1) + id
        float xh[32];
#pragma unroll
        for (int i = 0; i < 32; i++) xh[i] = 0.f;
        mv_mma(uX, uW + 8192, xh, lane);
        int row0 = rbase + rl;
#pragma unroll
        for (int j = 0; j < 8; j++) {
            float2 bb = ((const float2*)b1p)[j * 4 + cp];
            float2 i0 = __half22float2(g_idh[row0 * 32 + j * 4 + cp]);
            float2 i1 = __half22float2(g_idh[(row0 + 8) * 32 + j * 4 + cp]);
            xh[j * 4 + 0] = leaky(xh[j * 4 + 0] + bb.x) + i0.x;
            xh[j * 4 + 1] = leaky(xh[j * 4 + 1] + bb.y) + i0.y;
            xh[j * 4 + 2] = leaky(xh[j * 4 + 2] + bb.x) + i1.x;
            xh[j * 4 + 3] = leaky(xh[j * 4 + 3] + bb.y) + i1.y;
        }

        // ---- mv0: h = leaky(agg@W0^T + b0) -> fp16 restage into bufX
        float c2[32];
#pragma unroll
        for (int i = 0; i < 32; i++) c2[i] = 0.f;
        mv_mma(uA, uW, c2, lane);
        __syncwarp();
#pragma unroll
        for (int j = 0; j < 8; j++) {
            float2 bb = ((const float2*)b0p)[j * 4 + cp];
            __half2 h0 = __floats2half2_rn(leaky(c2[j * 4 + 0] + bb.x),
                                           leaky(c2[j * 4 + 1] + bb.y));
            __half2 h1 = __floats2half2_rn(leaky(c2[j * 4 + 2] + bb.x),
                                           leaky(c2[j * 4 + 3] + bb.y));
            int ch = (j ^ rlsw) << 4;
            *(__half2*)(bufX + rl * 128 + ch + cp * 4) = h0;
            *(__half2*)(bufX + (rl + 8) * 128 + ch + cp * 4) = h1;
        }
        __syncwarp();

        // ---- mv2: out = leaky(h@W2^T + b2 + xh)
#pragma unroll
        for (int j = 0; j < 8; j++) {
            float2 bb = ((const float2*)b2p)[j * 4 + cp];
            xh[j * 4 + 0] += bb.x;
            xh[j * 4 + 1] += bb.y;
            xh[j * 4 + 2] += bb.x;
            xh[j * 4 + 3] += bb.y;
        }
        mv_mma(uX, uW + 16384, xh, lane);
#pragma unroll
        for (int j = 0; j < 8; j++) {
            __half2 o0 = __floats2half2_rn(leaky(xh[j * 4 + 0]), leaky(xh[j * 4 + 1]));
            __half2 o1 = __floats2half2_rn(leaky(xh[j * 4 + 2]), leaky(xh[j * 4 + 3]));
            *(__half2*)(xo + (size_t)row0 * 256 + (j * 4 + cp) * 4) = o0;
            *(__half2*)(xo + (size_t)(row0 + 8) * 256 + (j * 4 + cp) * 4) = o1;
        }
    }
}

// ------------- final combine -------------------------------------------------
__global__ void k_combine(float2* __restrict__ out) {
    int i = blockIdx.x * blockDim.x + threadIdx.x;
    if (i < NN * 32) {
        int node = i >> 5, j = i & 31;
        float2 a = __half22float2(g_x[node * 64 + j]);
        float2 b = __half22float2(g_x[node * 64 + 32 + j]);
        out[i] = make_float2(0.5f * (a.x + b.x), 0.5f * (a.y + b.y));
    }
}

// ------------- launch --------------------------------------------------------
extern "C" void kernel_launch(void* const* d_in, const int* in_sizes, int n_in,
                              void* d_out, int out_size) {
    const float* v_feat = (const float*)d_in[0];
    const float* t_feat = (const float*)d_in[1];
    const float* id_emb = (const float*)d_in[2];
    const float* v_pref = (const float*)d_in[3];
    const float* t_pref = (const float*)d_in[4];
    const float* v_W    = (const float*)d_in[5];
    const float* v_b    = (const float*)d_in[6];
    const float* t_W    = (const float*)d_in[7];
    const float* t_b    = (const float*)d_in[8];
    const int*   edges  = (const int*)d_in[9];
    const int* row = edges;
    const int* col = edges + NE;
    float2* out = (float2*)d_out;

    void *degp, *statep;
    cudaGetSymbolAddress(&degp, g_deg);
    cudaGetSymbolAddress(&statep, g_state);

    static int attr_done = 0;
    if (!attr_done) {
        cudaFuncSetAttribute(k_dense, cudaFuncAttributeMaxDynamicSharedMemorySize,
                             DENSE_SMEM_BYTES);
        attr_done = 1;
    }

    cudaMemsetAsync(degp, 0, NN * sizeof(int));
    cudaMemsetAsync(statep, 0, NB_SCAN * sizeof(unsigned long long));

    k_init_hist<<<20000, 256>>>(v_pref, v_feat, t_pref, t_feat, id_emb, row);
    k_scan<<<NB_SCAN, 1024>>>();
    k_fill<<<(NE + 255) / 256, 256>>>(row, col);

    dim3 dgrid(125, 2);
    for (int layer = 0; layer < 2; layer++) {
        k_agg<<<5000, 512>>>();
        k_dense<<<dgrid, 256, DENSE_SMEM_BYTES>>>(
            v_W + layer * 3 * 4096, v_b + layer * 3 * 64,
            t_W + layer * 3 * 4096, t_b + layer * 3 * 64);
    }

    k_combine<<<10000, 256>>>(out);
}